// round 2
// baseline (speedup 1.0000x reference)
#include <cuda_runtime.h>
#include <math.h>

// Problem constants
#define Bb 64
#define Tt 512
#define Hh 1024
#define Mtot (Bb * Tt)   // 32768

// Scratch (device globals: no allocation allowed)
__device__ float g_scores[Mtot];
__device__ float g_alpha[Mtot];
__device__ float g_r[Bb * Hh];
__device__ float g_p[Bb * Hh];
__device__ float g_x[Bb * Hh];

// ---------------------------------------------------------------------------
// init: zero scores, preload biases into p/x accumulators
// ---------------------------------------------------------------------------
__global__ void init_kernel(const float* __restrict__ b_p,
                            const float* __restrict__ b_x) {
    int i = blockIdx.x * 256 + threadIdx.x;   // 65536 threads
    if (i < Mtot) g_scores[i] = 0.f;
    g_p[i] = b_p[i & (Hh - 1)];
    g_x[i] = b_x[i & (Hh - 1)];
}

// ---------------------------------------------------------------------------
// Big GEMM (M=32768, N=1024, K=1024) with fused tanh*w_w reduction epilogue.
// z[m,n] = hidden[m,:] . W_h[n,:] + b_h[n];  scores[m] += sum_n tanh(z)*w_w[n]
// Tile 128x128x16, 256 threads, 8x8 per thread (split 4+4 for LDS.128).
// ---------------------------------------------------------------------------
__global__ __launch_bounds__(256, 2)
void gemm_scores_kernel(const float* __restrict__ A,    // hidden [M,K]
                        const float* __restrict__ W,    // W_h [N,K]
                        const float* __restrict__ bh,   // [N]
                        const float* __restrict__ ww)   // w_w, first Hh entries
{
    const int K = Hh;
    __shared__ float As[16][128];
    __shared__ float Bs[16][128];
    __shared__ float s_red[128];

    int tid = threadIdx.x;
    int mBase = blockIdx.y * 128;
    int nBase = blockIdx.x * 128;

    int tn = tid & 15;   // col group
    int tm = tid >> 4;   // row group

    int lrow = tid >> 2;          // 0..63
    int lcol = (tid & 3) << 2;    // 0,4,8,12

    const float* Ag = A + (size_t)(mBase + lrow) * K + lcol;
    const float* Wg = W + (size_t)(nBase + lrow) * K + lcol;

    float acc[8][8];
#pragma unroll
    for (int i = 0; i < 8; i++)
#pragma unroll
        for (int j = 0; j < 8; j++) acc[i][j] = 0.f;

    for (int k0 = 0; k0 < K; k0 += 16) {
        float4 a0 = *(const float4*)(Ag + k0);
        float4 a1 = *(const float4*)(Ag + (size_t)64 * K + k0);
        float4 w0 = *(const float4*)(Wg + k0);
        float4 w1 = *(const float4*)(Wg + (size_t)64 * K + k0);
        __syncthreads();
        As[lcol + 0][lrow] = a0.x; As[lcol + 1][lrow] = a0.y;
        As[lcol + 2][lrow] = a0.z; As[lcol + 3][lrow] = a0.w;
        As[lcol + 0][lrow + 64] = a1.x; As[lcol + 1][lrow + 64] = a1.y;
        As[lcol + 2][lrow + 64] = a1.z; As[lcol + 3][lrow + 64] = a1.w;
        Bs[lcol + 0][lrow] = w0.x; Bs[lcol + 1][lrow] = w0.y;
        Bs[lcol + 2][lrow] = w0.z; Bs[lcol + 3][lrow] = w0.w;
        Bs[lcol + 0][lrow + 64] = w1.x; Bs[lcol + 1][lrow + 64] = w1.y;
        Bs[lcol + 2][lrow + 64] = w1.z; Bs[lcol + 3][lrow + 64] = w1.w;
        __syncthreads();
#pragma unroll
        for (int k = 0; k < 16; k++) {
            float4 ar0 = *(const float4*)&As[k][tm * 4];
            float4 ar1 = *(const float4*)&As[k][tm * 4 + 64];
            float4 br0 = *(const float4*)&Bs[k][tn * 4];
            float4 br1 = *(const float4*)&Bs[k][tn * 4 + 64];
            float ar[8] = {ar0.x, ar0.y, ar0.z, ar0.w, ar1.x, ar1.y, ar1.z, ar1.w};
            float br[8] = {br0.x, br0.y, br0.z, br0.w, br1.x, br1.y, br1.z, br1.w};
#pragma unroll
            for (int i = 0; i < 8; i++)
#pragma unroll
                for (int j = 0; j < 8; j++)
                    acc[i][j] = fmaf(ar[i], br[j], acc[i][j]);
        }
    }

    // fused epilogue: per-row partial of sum_n tanh(z)*ww
    float bh8[8], ww8[8];
#pragma unroll
    for (int j = 0; j < 8; j++) {
        int nl = (j < 4) ? (tn * 4 + j) : (64 + tn * 4 + j - 4);
        bh8[j] = bh[nBase + nl];
        ww8[j] = ww[nBase + nl];
    }
    __syncthreads();
    if (tid < 128) s_red[tid] = 0.f;
    __syncthreads();
#pragma unroll
    for (int i = 0; i < 8; i++) {
        int ml = (i < 4) ? (tm * 4 + i) : (64 + tm * 4 + i - 4);
        float part = 0.f;
#pragma unroll
        for (int j = 0; j < 8; j++)
            part += tanhf(acc[i][j] + bh8[j]) * ww8[j];
        atomicAdd(&s_red[ml], part);
    }
    __syncthreads();
    if (tid < 128)
        atomicAdd(&g_scores[mBase + tid], s_red[tid]);
}

// ---------------------------------------------------------------------------
// softmax over T per batch row
// ---------------------------------------------------------------------------
__global__ void softmax_kernel() {
    __shared__ float red[Tt];
    int b = blockIdx.x;
    int t = threadIdx.x;
    float s = g_scores[b * Tt + t];
    red[t] = s;
    __syncthreads();
    for (int off = 256; off > 0; off >>= 1) {
        if (t < off) red[t] = fmaxf(red[t], red[t + off]);
        __syncthreads();
    }
    float mx = red[0];
    __syncthreads();
    float e = expf(s - mx);
    red[t] = e;
    __syncthreads();
    for (int off = 256; off > 0; off >>= 1) {
        if (t < off) red[t] += red[t + off];
        __syncthreads();
    }
    g_alpha[b * Tt + t] = e / red[0];
}

// ---------------------------------------------------------------------------
// r[b,h] = sum_t alpha[b,t] * hidden[b,t,h]
// ---------------------------------------------------------------------------
__global__ void wsum_kernel(const float* __restrict__ hidden) {
    __shared__ float a_s[Tt];
    int b = blockIdx.y;
    int h = blockIdx.x * 256 + threadIdx.x;
    a_s[threadIdx.x] = g_alpha[b * Tt + threadIdx.x];
    a_s[threadIdx.x + 256] = g_alpha[b * Tt + threadIdx.x + 256];
    __syncthreads();
    const float* hp = hidden + (size_t)b * Tt * Hh + h;
    float acc0 = 0.f, acc1 = 0.f, acc2 = 0.f, acc3 = 0.f;
    for (int t = 0; t < Tt; t += 4) {
        acc0 += a_s[t + 0] * hp[(size_t)(t + 0) * Hh];
        acc1 += a_s[t + 1] * hp[(size_t)(t + 1) * Hh];
        acc2 += a_s[t + 2] * hp[(size_t)(t + 2) * Hh];
        acc3 += a_s[t + 3] * hp[(size_t)(t + 3) * Hh];
    }
    g_r[b * Hh + h] = (acc0 + acc1) + (acc2 + acc3);
}

// ---------------------------------------------------------------------------
// small GEMM: out[b,n] += V[b,:] . W[n,:]   (out pre-initialized with bias)
// sel==0: V=g_r (stride Hh), out=g_p.  sel==1: V=hidden last token, out=g_x.
// Tile: 64(b) x 64(n) x 128(k-split), grid (N/64, K/128)
// ---------------------------------------------------------------------------
__global__ __launch_bounds__(256)
void small_gemm_kernel(const float* __restrict__ hidden,
                       const float* __restrict__ W, int sel) {
    __shared__ float Vs[32][68];
    __shared__ float Ws[32][68];

    const float* V;
    size_t vstride;
    if (sel) { V = hidden + (size_t)(Tt - 1) * Hh; vstride = (size_t)Tt * Hh; }
    else     { V = g_r; vstride = Hh; }

    int tid = threadIdx.x;
    int nBase = blockIdx.x * 64;
    int kBase = blockIdx.y * 128;

    int tn = tid & 15;   // n quad
    int tb = tid >> 4;   // b quad

    int lrow = tid >> 3;          // 0..31
    int lcol = (tid & 7) << 2;    // 0..28

    float acc[4][4];
#pragma unroll
    for (int i = 0; i < 4; i++)
#pragma unroll
        for (int j = 0; j < 4; j++) acc[i][j] = 0.f;

    for (int kc = 0; kc < 128; kc += 32) {
        int kg = kBase + kc;
        float4 v0 = *(const float4*)(V + (size_t)lrow * vstride + kg + lcol);
        float4 v1 = *(const float4*)(V + (size_t)(lrow + 32) * vstride + kg + lcol);
        float4 w0 = *(const float4*)(W + (size_t)(nBase + lrow) * Hh + kg + lcol);
        float4 w1 = *(const float4*)(W + (size_t)(nBase + lrow + 32) * Hh + kg + lcol);
        __syncthreads();
        Vs[lcol + 0][lrow] = v0.x; Vs[lcol + 1][lrow] = v0.y;
        Vs[lcol + 2][lrow] = v0.z; Vs[lcol + 3][lrow] = v0.w;
        Vs[lcol + 0][lrow + 32] = v1.x; Vs[lcol + 1][lrow + 32] = v1.y;
        Vs[lcol + 2][lrow + 32] = v1.z; Vs[lcol + 3][lrow + 32] = v1.w;
        Ws[lcol + 0][lrow] = w0.x; Ws[lcol + 1][lrow] = w0.y;
        Ws[lcol + 2][lrow] = w0.z; Ws[lcol + 3][lrow] = w0.w;
        Ws[lcol + 0][lrow + 32] = w1.x; Ws[lcol + 1][lrow + 32] = w1.y;
        Ws[lcol + 2][lrow + 32] = w1.z; Ws[lcol + 3][lrow + 32] = w1.w;
        __syncthreads();
#pragma unroll
        for (int k = 0; k < 32; k++) {
            float vb[4], wn[4];
#pragma unroll
            for (int i = 0; i < 4; i++) vb[i] = Vs[k][tb * 4 + i];
#pragma unroll
            for (int j = 0; j < 4; j++) wn[j] = Ws[k][tn * 4 + j];
#pragma unroll
            for (int i = 0; i < 4; i++)
#pragma unroll
                for (int j = 0; j < 4; j++)
                    acc[i][j] = fmaf(vb[i], wn[j], acc[i][j]);
        }
    }

    float* out = sel ? g_x : g_p;
#pragma unroll
    for (int i = 0; i < 4; i++)
#pragma unroll
        for (int j = 0; j < 4; j++)
            atomicAdd(&out[(tb * 4 + i) * Hh + nBase + tn * 4 + j], acc[i][j]);
}

// ---------------------------------------------------------------------------
// output[b1,b2,h] = tanh(p[b1,h] + x[b2,h])   (the [B,1,H]+[B,H] quirk)
// ---------------------------------------------------------------------------
__global__ void output_kernel(float* __restrict__ out) {
    int h = blockIdx.x * 256 + threadIdx.x;
    int b2 = blockIdx.y;
    int b1 = blockIdx.z;
    out[((size_t)b1 * Bb + b2) * Hh + h] =
        tanhf(g_p[b1 * Hh + h] + g_x[b2 * Hh + h]);
}

// ---------------------------------------------------------------------------
// launch
// ---------------------------------------------------------------------------
extern "C" void kernel_launch(void* const* d_in, const int* in_sizes, int n_in,
                              void* d_out, int out_size) {
    (void)in_sizes; (void)n_in; (void)out_size;
    const float* hidden = (const float*)d_in[0];
    // d_in[1] aspect, d_in[4] W_v, d_in[5] b_v, d_in[7] w_b: provably dead
    // (softmax shift-invariance kills the per-batch-constant aspect branch).
    const float* W_h = (const float*)d_in[2];
    const float* b_h = (const float*)d_in[3];
    const float* w_w = (const float*)d_in[6];   // use first Hh entries
    const float* W_p = (const float*)d_in[8];
    const float* b_p = (const float*)d_in[9];
    const float* W_x = (const float*)d_in[10];
    const float* b_x = (const float*)d_in[11];
    float* out = (float*)d_out;

    init_kernel<<<256, 256>>>(b_p, b_x);
    gemm_scores_kernel<<<dim3(Hh / 128, Mtot / 128), 256>>>(hidden, W_h, b_h, w_w);
    softmax_kernel<<<Bb, Tt>>>();
    wsum_kernel<<<dim3(Hh / 256, Bb), 256>>>(hidden);
    small_gemm_kernel<<<dim3(Hh / 64, Hh / 128), 256>>>(hidden, W_p, 0);
    small_gemm_kernel<<<dim3(Hh / 64, Hh / 128), 256>>>(hidden, W_x, 1);
    output_kernel<<<dim3(Hh / 256, Bb, Bb), 256>>>(out);
}

// round 5
// speedup vs baseline: 6.1663x; 6.1663x over previous
#include <cuda_runtime.h>
#include <math.h>
#include <stdint.h>

// ---------------------------------------------------------------------------
// Problem constants
// ---------------------------------------------------------------------------
#define Bb 64
#define Tt 512
#define Hh 1024
#define Mtot (Bb * Tt)   // 32768

// Big-GEMM tiling (legacy mma.sync tf32 path — compute_103-safe PTX only)
#define MT 128
#define NT 256
#define KC 32
#define NSTG 4
#define KCHUNKS (Hh / KC)          // 32
#define GX (Hh / NT)               // 4
#define A_FLOATS (MT * KC)         // 4096
#define STG_FLOATS ((MT + NT) * KC) // 12288 floats = 48KB/stage
#define SMEM_FLOATS (NSTG * STG_FLOATS + 128)
#define SMEM_BYTES (SMEM_FLOATS * 4)   // 196608 + 512

// ---------------------------------------------------------------------------
// Scratch (device globals: no allocation allowed)
// ---------------------------------------------------------------------------
__device__ float g_spart[GX * Mtot];   // per-N-tile partial scores
__device__ float g_alpha[Mtot];
__device__ float g_r[Bb * Hh];
__device__ float g_p[Bb * Hh];
__device__ float g_x[Bb * Hh];

// ---------------------------------------------------------------------------
// helpers
// ---------------------------------------------------------------------------
__device__ __forceinline__ uint32_t smem_u32(const void* p) {
    uint32_t a;
    asm("{ .reg .u64 t; cvta.to.shared.u64 t, %1; cvt.u32.u64 %0, t; }" : "=r"(a) : "l"(p));
    return a;
}
__device__ __forceinline__ float tanh_fast(float x) {
    float y;
    asm("tanh.approx.f32 %0, %1;" : "=f"(y) : "f"(x));
    return y;
}

// ---------------------------------------------------------------------------
// init: zero r accumulator, preload biases into p/x accumulators
// ---------------------------------------------------------------------------
__global__ void init_kernel(const float* __restrict__ b_p,
                            const float* __restrict__ b_x) {
    int i = blockIdx.x * 256 + threadIdx.x;   // 65536 threads
    g_r[i] = 0.f;
    g_p[i] = b_p[i & (Hh - 1)];
    g_x[i] = b_x[i & (Hh - 1)];
}

// ---------------------------------------------------------------------------
// Big GEMM (M=32768,N=1024,K=1024) on mma.sync tf32 with fused tanh*w_w
// score-reduction epilogue. CTA tile 128x256xK, 8 warps (warp tile 64x64),
// 4-stage cp.async pipeline, XOR-swizzled smem (conflict-free frag loads).
// ---------------------------------------------------------------------------
__global__ __launch_bounds__(256, 1)
void gemm_scores_tc(const float* __restrict__ A,    // hidden [M,K]
                    const float* __restrict__ W,    // W_h [N,K]
                    const float* __restrict__ bh,
                    const float* __restrict__ ww) {
    extern __shared__ float sm[];
    float* s_red = sm + NSTG * STG_FLOATS;

    int tid = threadIdx.x;
    int w = tid >> 5, lane = tid & 31;
    int gid = lane >> 2, tig = lane & 3;
    int wm = (w >> 2) * 64;         // 0 / 64
    int wn = (w & 3) * 64;          // 0..192
    int m0 = blockIdx.y * MT;
    int n0 = blockIdx.x * NT;

    if (tid < 128) s_red[tid] = 0.f;

    uint32_t sbase = smem_u32(sm);
    const char* Ab = (const char*)(A + (size_t)m0 * Hh);
    const char* Wb = (const char*)(W + (size_t)n0 * Hh);

    auto issue = [&](int s, int kidx) {
        uint32_t aS = sbase + s * (STG_FLOATS * 4);
        uint32_t bS = aS + A_FLOATS * 4;
        int kb = kidx * (KC * 4);
#pragma unroll
        for (int u = 0; u < 4; u++) {            // A: 1024 chunks of 16B
            int c = tid + u * 256;
            int row = c >> 3, ch = c & 7;
            const char* g = Ab + (size_t)row * (Hh * 4) + kb + ch * 16;
            uint32_t d = aS + row * 128 + ((ch ^ (row & 7)) * 16);
            asm volatile("cp.async.cg.shared.global [%0], [%1], 16;" :: "r"(d), "l"(g));
        }
#pragma unroll
        for (int u = 0; u < 8; u++) {            // B: 2048 chunks
            int c = tid + u * 256;
            int row = c >> 3, ch = c & 7;
            const char* g = Wb + (size_t)row * (Hh * 4) + kb + ch * 16;
            uint32_t d = bS + row * 128 + ((ch ^ (row & 7)) * 16);
            asm volatile("cp.async.cg.shared.global [%0], [%1], 16;" :: "r"(d), "l"(g));
        }
        asm volatile("cp.async.commit_group;" ::: "memory");
    };

    issue(0, 0); issue(1, 1); issue(2, 2);

    float acc[4][8][4];
#pragma unroll
    for (int i = 0; i < 4; i++)
#pragma unroll
        for (int j = 0; j < 8; j++)
#pragma unroll
            for (int r = 0; r < 4; r++) acc[i][j][r] = 0.f;

    int aOff[4], bOff[8];
#pragma unroll
    for (int i = 0; i < 4; i++) aOff[i] = (wm + i * 16 + gid) * 32 + tig;
#pragma unroll
    for (int j = 0; j < 8; j++) bOff[j] = (wn + j * 8 + gid) * 32 + tig;

    for (int ks = 0; ks < KCHUNKS; ks++) {
        if (ks <= KCHUNKS - 3)
            asm volatile("cp.async.wait_group 2;" ::: "memory");
        else if (ks == KCHUNKS - 2)
            asm volatile("cp.async.wait_group 1;" ::: "memory");
        else
            asm volatile("cp.async.wait_group 0;" ::: "memory");
        __syncthreads();
        if (ks + 3 < KCHUNKS) issue((ks + 3) & 3, ks + 3);

        const float* Sa = sm + (ks & 3) * STG_FLOATS;
        const float* Sb = Sa + A_FLOATS;
#pragma unroll
        for (int kk = 0; kk < 4; kk++) {
            int sw0 = ((2 * kk) ^ gid) * 4;
            int sw1 = ((2 * kk + 1) ^ gid) * 4;
            uint32_t af[4][4];
#pragma unroll
            for (int i = 0; i < 4; i++) {
                af[i][0] = __float_as_uint(Sa[aOff[i] + sw0]);
                af[i][1] = __float_as_uint(Sa[aOff[i] + 256 + sw0]);
                af[i][2] = __float_as_uint(Sa[aOff[i] + sw1]);
                af[i][3] = __float_as_uint(Sa[aOff[i] + 256 + sw1]);
            }
            uint32_t bfr[8][2];
#pragma unroll
            for (int j = 0; j < 8; j++) {
                bfr[j][0] = __float_as_uint(Sb[bOff[j] + sw0]);
                bfr[j][1] = __float_as_uint(Sb[bOff[j] + sw1]);
            }
#pragma unroll
            for (int i = 0; i < 4; i++)
#pragma unroll
                for (int j = 0; j < 8; j++)
                    asm volatile(
                        "mma.sync.aligned.m16n8k8.row.col.f32.tf32.tf32.f32 "
                        "{%0,%1,%2,%3}, {%4,%5,%6,%7}, {%8,%9}, {%0,%1,%2,%3};"
                        : "+f"(acc[i][j][0]), "+f"(acc[i][j][1]),
                          "+f"(acc[i][j][2]), "+f"(acc[i][j][3])
                        : "r"(af[i][0]), "r"(af[i][1]), "r"(af[i][2]), "r"(af[i][3]),
                          "r"(bfr[j][0]), "r"(bfr[j][1]));
        }
    }

    // Fused epilogue: part[m] = sum_n tanh(acc + bh[n]) * ww[n]
    float bhv[8][2], wwv[8][2];
#pragma unroll
    for (int j = 0; j < 8; j++) {
#pragma unroll
        for (int h = 0; h < 2; h++) {
            int n = n0 + wn + j * 8 + 2 * tig + h;
            bhv[j][h] = bh[n];
            wwv[j][h] = ww[n];
        }
    }
#pragma unroll
    for (int i = 0; i < 4; i++) {
        float p0 = 0.f, p1 = 0.f;
#pragma unroll
        for (int j = 0; j < 8; j++) {
            p0 += tanh_fast(acc[i][j][0] + bhv[j][0]) * wwv[j][0];
            p0 += tanh_fast(acc[i][j][1] + bhv[j][1]) * wwv[j][1];
            p1 += tanh_fast(acc[i][j][2] + bhv[j][0]) * wwv[j][0];
            p1 += tanh_fast(acc[i][j][3] + bhv[j][1]) * wwv[j][1];
        }
        p0 += __shfl_xor_sync(0xffffffffu, p0, 1);
        p0 += __shfl_xor_sync(0xffffffffu, p0, 2);
        p1 += __shfl_xor_sync(0xffffffffu, p1, 1);
        p1 += __shfl_xor_sync(0xffffffffu, p1, 2);
        if (tig == 0) {
            atomicAdd(&s_red[wm + i * 16 + gid], p0);
            atomicAdd(&s_red[wm + i * 16 + gid + 8], p1);
        }
    }
    __syncthreads();
    if (tid < 128)
        g_spart[blockIdx.x * Mtot + m0 + tid] = s_red[tid];
}

// ---------------------------------------------------------------------------
// softmax over T per batch row (sums the GX partial-score slabs)
// ---------------------------------------------------------------------------
__global__ void softmax_kernel() {
    __shared__ float red[Tt];
    int b = blockIdx.x;
    int t = threadIdx.x;
    float s = 0.f;
#pragma unroll
    for (int p = 0; p < GX; p++) s += g_spart[p * Mtot + b * Tt + t];
    red[t] = s;
    __syncthreads();
    for (int off = 256; off > 0; off >>= 1) {
        if (t < off) red[t] = fmaxf(red[t], red[t + off]);
        __syncthreads();
    }
    float mx = red[0];
    __syncthreads();
    float e = expf(s - mx);
    red[t] = e;
    __syncthreads();
    for (int off = 256; off > 0; off >>= 1) {
        if (t < off) red[t] += red[t + off];
        __syncthreads();
    }
    g_alpha[b * Tt + t] = e / red[0];
}

// ---------------------------------------------------------------------------
// r[b,h] += sum_t alpha[b,t]*hidden[b,t,h], T split 4 ways for MLP
// ---------------------------------------------------------------------------
__global__ void wsum_kernel(const float* __restrict__ hidden) {
    __shared__ float a_s[128];
    int seg = blockIdx.z;
    int b = blockIdx.y;
    int h = blockIdx.x * 256 + threadIdx.x;
    if (threadIdx.x < 128) a_s[threadIdx.x] = g_alpha[b * Tt + seg * 128 + threadIdx.x];
    __syncthreads();
    const float* hp = hidden + ((size_t)b * Tt + seg * 128) * Hh + h;
    float acc[8];
#pragma unroll
    for (int u = 0; u < 8; u++) acc[u] = 0.f;
    for (int t = 0; t < 128; t += 8) {
#pragma unroll
        for (int u = 0; u < 8; u++)
            acc[u] += a_s[t + u] * hp[(size_t)(t + u) * Hh];
    }
    float sum = ((acc[0] + acc[1]) + (acc[2] + acc[3])) +
                ((acc[4] + acc[5]) + (acc[6] + acc[7]));
    atomicAdd(&g_r[b * Hh + h], sum);
}

// ---------------------------------------------------------------------------
// small GEMM: out[b,n] += V[b,:] . W[n,:]   (out pre-initialized with bias)
// ---------------------------------------------------------------------------
__global__ __launch_bounds__(256)
void small_gemm_kernel(const float* __restrict__ hidden,
                       const float* __restrict__ W, int sel) {
    __shared__ float Vs[32][68];
    __shared__ float Ws[32][68];

    const float* V;
    size_t vstride;
    if (sel) { V = hidden + (size_t)(Tt - 1) * Hh; vstride = (size_t)Tt * Hh; }
    else     { V = g_r; vstride = Hh; }

    int tid = threadIdx.x;
    int nBase = blockIdx.x * 64;
    int kBase = blockIdx.y * 128;

    int tn = tid & 15;
    int tb = tid >> 4;
    int lrow = tid >> 3;
    int lcol = (tid & 7) << 2;

    float acc[4][4];
#pragma unroll
    for (int i = 0; i < 4; i++)
#pragma unroll
        for (int j = 0; j < 4; j++) acc[i][j] = 0.f;

    for (int kc = 0; kc < 128; kc += 32) {
        int kg = kBase + kc;
        float4 v0 = *(const float4*)(V + (size_t)lrow * vstride + kg + lcol);
        float4 v1 = *(const float4*)(V + (size_t)(lrow + 32) * vstride + kg + lcol);
        float4 w0 = *(const float4*)(W + (size_t)(nBase + lrow) * Hh + kg + lcol);
        float4 w1 = *(const float4*)(W + (size_t)(nBase + lrow + 32) * Hh + kg + lcol);
        __syncthreads();
        Vs[lcol + 0][lrow] = v0.x; Vs[lcol + 1][lrow] = v0.y;
        Vs[lcol + 2][lrow] = v0.z; Vs[lcol + 3][lrow] = v0.w;
        Vs[lcol + 0][lrow + 32] = v1.x; Vs[lcol + 1][lrow + 32] = v1.y;
        Vs[lcol + 2][lrow + 32] = v1.z; Vs[lcol + 3][lrow + 32] = v1.w;
        Ws[lcol + 0][lrow] = w0.x; Ws[lcol + 1][lrow] = w0.y;
        Ws[lcol + 2][lrow] = w0.z; Ws[lcol + 3][lrow] = w0.w;
        Ws[lcol + 0][lrow + 32] = w1.x; Ws[lcol + 1][lrow + 32] = w1.y;
        Ws[lcol + 2][lrow + 32] = w1.z; Ws[lcol + 3][lrow + 32] = w1.w;
        __syncthreads();
#pragma unroll
        for (int k = 0; k < 32; k++) {
            float vb[4], wnv[4];
#pragma unroll
            for (int i = 0; i < 4; i++) vb[i] = Vs[k][tb * 4 + i];
#pragma unroll
            for (int j = 0; j < 4; j++) wnv[j] = Ws[k][tn * 4 + j];
#pragma unroll
            for (int i = 0; i < 4; i++)
#pragma unroll
                for (int j = 0; j < 4; j++)
                    acc[i][j] = fmaf(vb[i], wnv[j], acc[i][j]);
        }
    }

    float* out = sel ? g_x : g_p;
#pragma unroll
    for (int i = 0; i < 4; i++)
#pragma unroll
        for (int j = 0; j < 4; j++)
            atomicAdd(&out[(tb * 4 + i) * Hh + nBase + tn * 4 + j], acc[i][j]);
}

// ---------------------------------------------------------------------------
// output[b1,b2,h] = tanh(p[b1,h] + x[b2,h])
// ---------------------------------------------------------------------------
__global__ void output_kernel(float* __restrict__ out) {
    int h = blockIdx.x * 256 + threadIdx.x;
    int b2 = blockIdx.y;
    int b1 = blockIdx.z;
    out[((size_t)b1 * Bb + b2) * Hh + h] =
        tanhf(g_p[b1 * Hh + h] + g_x[b2 * Hh + h]);
}

// ---------------------------------------------------------------------------
// launch
// ---------------------------------------------------------------------------
extern "C" void kernel_launch(void* const* d_in, const int* in_sizes, int n_in,
                              void* d_out, int out_size) {
    (void)in_sizes; (void)n_in; (void)out_size;
    const float* hidden = (const float*)d_in[0];
    // d_in[1] aspect, d_in[4] W_v, d_in[5] b_v, d_in[7] w_b are provably dead
    // (softmax shift-invariance kills the per-batch-constant aspect branch).
    const float* W_h = (const float*)d_in[2];
    const float* b_h = (const float*)d_in[3];
    const float* w_w = (const float*)d_in[6];
    const float* W_p = (const float*)d_in[8];
    const float* b_p = (const float*)d_in[9];
    const float* W_x = (const float*)d_in[10];
    const float* b_x = (const float*)d_in[11];
    float* out = (float*)d_out;

    cudaFuncSetAttribute(gemm_scores_tc,
                         cudaFuncAttributeMaxDynamicSharedMemorySize, SMEM_BYTES);

    init_kernel<<<256, 256>>>(b_p, b_x);
    gemm_scores_tc<<<dim3(GX, Mtot / MT), 256, SMEM_BYTES>>>(hidden, W_h, b_h, w_w);
    softmax_kernel<<<Bb, Tt>>>();
    wsum_kernel<<<dim3(Hh / 256, Bb, 4), 256>>>(hidden);
    small_gemm_kernel<<<dim3(Hh / 64, Hh / 128), 256>>>(hidden, W_p, 0);
    small_gemm_kernel<<<dim3(Hh / 64, Hh / 128), 256>>>(hidden, W_x, 1);
    output_kernel<<<dim3(Hh / 256, Bb, Bb), 256>>>(out);
}

// round 6
// speedup vs baseline: 9.0373x; 1.4656x over previous
#include <cuda_runtime.h>
#include <cuda_bf16.h>
#include <math.h>
#include <stdint.h>

// ---------------------------------------------------------------------------
// Problem constants
// ---------------------------------------------------------------------------
#define Bb 64
#define Tt 512
#define Hh 1024
#define Mtot (Bb * Tt)   // 32768

// Big-GEMM tiling (legacy mma.sync bf16 path — compute_103-safe PTX only)
#define MT 128
#define NT 256
#define KC 64                       // K per smem stage (64 bf16 = 128B rows)
#define NSTG 4
#define KCHUNKS (Hh / KC)           // 16
#define GX (Hh / NT)                // 4
#define A_U32 (MT * KC / 2)         // 4096 uint32 (bf16 pairs)
#define STG_U32 ((MT + NT) * KC / 2)  // 12288 uint32 = 48KB/stage
#define SMEM_U32 (NSTG * STG_U32 + 128)
#define SMEM_BYTES (SMEM_U32 * 4)

// ---------------------------------------------------------------------------
// Scratch (device globals: no allocation allowed)
// ---------------------------------------------------------------------------
__device__ __align__(256) __nv_bfloat16 g_hbf[(size_t)Mtot * Hh];  // 64MB
__device__ __align__(256) __nv_bfloat16 g_wbf[(size_t)Hh * Hh];    // 2MB
__device__ float g_spart[GX * Mtot];   // per-N-tile partial scores
__device__ float g_alpha[Mtot];
__device__ float g_r[Bb * Hh];
__device__ float g_p[Bb * Hh];
__device__ float g_x[Bb * Hh];

// ---------------------------------------------------------------------------
// helpers
// ---------------------------------------------------------------------------
__device__ __forceinline__ uint32_t smem_u32(const void* p) {
    uint32_t a;
    asm("{ .reg .u64 t; cvta.to.shared.u64 t, %1; cvt.u32.u64 %0, t; }" : "=r"(a) : "l"(p));
    return a;
}
__device__ __forceinline__ float tanh_fast(float x) {
    float y;
    asm("tanh.approx.f32 %0, %1;" : "=f"(y) : "f"(x));
    return y;
}
__device__ __forceinline__ uint32_t pack_bf2(float lo, float hi) {
    __nv_bfloat162 v = __float22bfloat162_rn(make_float2(lo, hi));
    return *(uint32_t*)&v;
}

// ---------------------------------------------------------------------------
// fp32 -> bf16 streaming convert (8 elems/thread)
// ---------------------------------------------------------------------------
__global__ void cvt_kernel(const float* __restrict__ s, __nv_bfloat16* __restrict__ d) {
    size_t i = (size_t)blockIdx.x * 256 + threadIdx.x;
    const float4* s4 = (const float4*)s;
    float4 v0 = s4[2 * i], v1 = s4[2 * i + 1];
    uint4 o;
    o.x = pack_bf2(v0.x, v0.y);
    o.y = pack_bf2(v0.z, v0.w);
    o.z = pack_bf2(v1.x, v1.y);
    o.w = pack_bf2(v1.z, v1.w);
    ((uint4*)d)[i] = o;
}

// ---------------------------------------------------------------------------
// init: zero r accumulator, preload biases into p/x accumulators
// ---------------------------------------------------------------------------
__global__ void init_kernel(const float* __restrict__ b_p,
                            const float* __restrict__ b_x) {
    int i = blockIdx.x * 256 + threadIdx.x;   // 65536 threads
    g_r[i] = 0.f;
    g_p[i] = b_p[i & (Hh - 1)];
    g_x[i] = b_x[i & (Hh - 1)];
}

// ---------------------------------------------------------------------------
// Big GEMM (M=32768,N=1024,K=1024) on mma.sync m16n8k16 bf16, fused
// tanh*w_w score-reduction epilogue. CTA tile 128x256, 8 warps (64x64 each),
// 4-stage cp.async pipeline, XOR-swizzled smem (conflict-free frag loads).
// ---------------------------------------------------------------------------
__global__ __launch_bounds__(256, 1)
void gemm_scores_tc(const float* __restrict__ bh,
                    const float* __restrict__ ww) {
    extern __shared__ uint32_t sm[];
    float* s_red = (float*)(sm + NSTG * STG_U32);

    int tid = threadIdx.x;
    int w = tid >> 5, lane = tid & 31;
    int gid = lane >> 2, tig = lane & 3;
    int wm = (w >> 2) * 64;         // 0 / 64
    int wn = (w & 3) * 64;          // 0..192
    int m0 = blockIdx.y * MT;
    int n0 = blockIdx.x * NT;

    if (tid < 128) s_red[tid] = 0.f;

    uint32_t sbase = smem_u32(sm);
    const char* Ab = (const char*)(g_hbf + (size_t)m0 * Hh);
    const char* Wb = (const char*)(g_wbf + (size_t)n0 * Hh);

    auto issue = [&](int s, int kidx) {
        uint32_t aS = sbase + s * (STG_U32 * 4);
        uint32_t bS = aS + A_U32 * 4;
        int kb = kidx * (KC * 2);               // bytes along K
#pragma unroll
        for (int u = 0; u < 4; u++) {           // A: 1024 chunks of 16B
            int c = tid + u * 256;
            int row = c >> 3, ch = c & 7;
            const char* g = Ab + (size_t)row * (Hh * 2) + kb + ch * 16;
            uint32_t d = aS + row * 128 + ((ch ^ (row & 7)) * 16);
            asm volatile("cp.async.cg.shared.global [%0], [%1], 16;" :: "r"(d), "l"(g));
        }
#pragma unroll
        for (int u = 0; u < 8; u++) {           // B: 2048 chunks
            int c = tid + u * 256;
            int row = c >> 3, ch = c & 7;
            const char* g = Wb + (size_t)row * (Hh * 2) + kb + ch * 16;
            uint32_t d = bS + row * 128 + ((ch ^ (row & 7)) * 16);
            asm volatile("cp.async.cg.shared.global [%0], [%1], 16;" :: "r"(d), "l"(g));
        }
        asm volatile("cp.async.commit_group;" ::: "memory");
    };

    issue(0, 0); issue(1, 1); issue(2, 2);

    float acc[4][8][4];
#pragma unroll
    for (int i = 0; i < 4; i++)
#pragma unroll
        for (int j = 0; j < 8; j++)
#pragma unroll
            for (int r = 0; r < 4; r++) acc[i][j][r] = 0.f;

    int aOff[4], bOff[8];
#pragma unroll
    for (int i = 0; i < 4; i++) aOff[i] = (wm + i * 16 + gid) * 32 + tig;
#pragma unroll
    for (int j = 0; j < 8; j++) bOff[j] = (wn + j * 8 + gid) * 32 + tig;

    for (int ks = 0; ks < KCHUNKS; ks++) {
        if (ks <= KCHUNKS - 3)
            asm volatile("cp.async.wait_group 2;" ::: "memory");
        else if (ks == KCHUNKS - 2)
            asm volatile("cp.async.wait_group 1;" ::: "memory");
        else
            asm volatile("cp.async.wait_group 0;" ::: "memory");
        __syncthreads();
        if (ks + 3 < KCHUNKS) issue((ks + 3) & 3, ks + 3);

        const uint32_t* Sa = sm + (ks & 3) * STG_U32;
        const uint32_t* Sb = Sa + A_U32;
        // 4 k-steps of 16 (chunk covers K=64): step kk uses 16B-groups 2kk, 2kk+1
#pragma unroll
        for (int kk = 0; kk < 4; kk++) {
            int sw0 = ((2 * kk) ^ gid) * 4;
            int sw1 = ((2 * kk + 1) ^ gid) * 4;
            uint32_t af[4][4];
#pragma unroll
            for (int i = 0; i < 4; i++) {
                af[i][0] = Sa[aOff[i] + sw0];          // (m=gid row,  k lo)
                af[i][1] = Sa[aOff[i] + 256 + sw0];    // (m=gid+8,    k lo)
                af[i][2] = Sa[aOff[i] + sw1];          // (m=gid row,  k hi)
                af[i][3] = Sa[aOff[i] + 256 + sw1];    // (m=gid+8,    k hi)
            }
            uint32_t bfr[8][2];
#pragma unroll
            for (int j = 0; j < 8; j++) {
                bfr[j][0] = Sb[bOff[j] + sw0];
                bfr[j][1] = Sb[bOff[j] + sw1];
            }
#pragma unroll
            for (int i = 0; i < 4; i++)
#pragma unroll
                for (int j = 0; j < 8; j++)
                    asm volatile(
                        "mma.sync.aligned.m16n8k16.row.col.f32.bf16.bf16.f32 "
                        "{%0,%1,%2,%3}, {%4,%5,%6,%7}, {%8,%9}, {%0,%1,%2,%3};"
                        : "+f"(acc[i][j][0]), "+f"(acc[i][j][1]),
                          "+f"(acc[i][j][2]), "+f"(acc[i][j][3])
                        : "r"(af[i][0]), "r"(af[i][1]), "r"(af[i][2]), "r"(af[i][3]),
                          "r"(bfr[j][0]), "r"(bfr[j][1]));
        }
    }

    // Fused epilogue: part[m] = sum_n tanh(acc + bh[n]) * ww[n]
    float bhv[8][2], wwv[8][2];
#pragma unroll
    for (int j = 0; j < 8; j++) {
#pragma unroll
        for (int h = 0; h < 2; h++) {
            int n = n0 + wn + j * 8 + 2 * tig + h;
            bhv[j][h] = bh[n];
            wwv[j][h] = ww[n];
        }
    }
#pragma unroll
    for (int i = 0; i < 4; i++) {
        float p0 = 0.f, p1 = 0.f;
#pragma unroll
        for (int j = 0; j < 8; j++) {
            p0 += tanh_fast(acc[i][j][0] + bhv[j][0]) * wwv[j][0];
            p0 += tanh_fast(acc[i][j][1] + bhv[j][1]) * wwv[j][1];
            p1 += tanh_fast(acc[i][j][2] + bhv[j][0]) * wwv[j][0];
            p1 += tanh_fast(acc[i][j][3] + bhv[j][1]) * wwv[j][1];
        }
        p0 += __shfl_xor_sync(0xffffffffu, p0, 1);
        p0 += __shfl_xor_sync(0xffffffffu, p0, 2);
        p1 += __shfl_xor_sync(0xffffffffu, p1, 1);
        p1 += __shfl_xor_sync(0xffffffffu, p1, 2);
        if (tig == 0) {
            atomicAdd(&s_red[wm + i * 16 + gid], p0);
            atomicAdd(&s_red[wm + i * 16 + gid + 8], p1);
        }
    }
    __syncthreads();
    if (tid < 128)
        g_spart[blockIdx.x * Mtot + m0 + tid] = s_red[tid];
}

// ---------------------------------------------------------------------------
// softmax over T per batch row (sums the GX partial-score slabs)
// ---------------------------------------------------------------------------
__global__ void softmax_kernel() {
    __shared__ float red[Tt];
    int b = blockIdx.x;
    int t = threadIdx.x;
    float s = 0.f;
#pragma unroll
    for (int p = 0; p < GX; p++) s += g_spart[p * Mtot + b * Tt + t];
    red[t] = s;
    __syncthreads();
    for (int off = 256; off > 0; off >>= 1) {
        if (t < off) red[t] = fmaxf(red[t], red[t + off]);
        __syncthreads();
    }
    float mx = red[0];
    __syncthreads();
    float e = expf(s - mx);
    red[t] = e;
    __syncthreads();
    for (int off = 256; off > 0; off >>= 1) {
        if (t < off) red[t] += red[t + off];
        __syncthreads();
    }
    g_alpha[b * Tt + t] = e / red[0];
}

// ---------------------------------------------------------------------------
// r[b,h] += sum_t alpha[b,t]*hidden[b,t,h], T split 4 ways for MLP
// ---------------------------------------------------------------------------
__global__ void wsum_kernel(const float* __restrict__ hidden) {
    __shared__ float a_s[128];
    int seg = blockIdx.z;
    int b = blockIdx.y;
    int h = blockIdx.x * 256 + threadIdx.x;
    if (threadIdx.x < 128) a_s[threadIdx.x] = g_alpha[b * Tt + seg * 128 + threadIdx.x];
    __syncthreads();
    const float* hp = hidden + ((size_t)b * Tt + seg * 128) * Hh + h;
    float acc[8];
#pragma unroll
    for (int u = 0; u < 8; u++) acc[u] = 0.f;
    for (int t = 0; t < 128; t += 8) {
#pragma unroll
        for (int u = 0; u < 8; u++)
            acc[u] += a_s[t + u] * hp[(size_t)(t + u) * Hh];
    }
    float sum = ((acc[0] + acc[1]) + (acc[2] + acc[3])) +
                ((acc[4] + acc[5]) + (acc[6] + acc[7]));
    atomicAdd(&g_r[b * Hh + h], sum);
}

// ---------------------------------------------------------------------------
// small GEMM: out[b,n] += V[b,:] . W[n,:]   (out pre-initialized with bias)
// ---------------------------------------------------------------------------
__global__ __launch_bounds__(256)
void small_gemm_kernel(const float* __restrict__ hidden,
                       const float* __restrict__ W, int sel) {
    __shared__ float Vs[32][68];
    __shared__ float Ws[32][68];

    const float* V;
    size_t vstride;
    if (sel) { V = hidden + (size_t)(Tt - 1) * Hh; vstride = (size_t)Tt * Hh; }
    else     { V = g_r; vstride = Hh; }

    int tid = threadIdx.x;
    int nBase = blockIdx.x * 64;
    int kBase = blockIdx.y * 128;

    int tn = tid & 15;
    int tb = tid >> 4;
    int lrow = tid >> 3;
    int lcol = (tid & 7) << 2;

    float acc[4][4];
#pragma unroll
    for (int i = 0; i < 4; i++)
#pragma unroll
        for (int j = 0; j < 4; j++) acc[i][j] = 0.f;

    for (int kc = 0; kc < 128; kc += 32) {
        int kg = kBase + kc;
        float4 v0 = *(const float4*)(V + (size_t)lrow * vstride + kg + lcol);
        float4 v1 = *(const float4*)(V + (size_t)(lrow + 32) * vstride + kg + lcol);
        float4 w0 = *(const float4*)(W + (size_t)(nBase + lrow) * Hh + kg + lcol);
        float4 w1 = *(const float4*)(W + (size_t)(nBase + lrow + 32) * Hh + kg + lcol);
        __syncthreads();
        Vs[lcol + 0][lrow] = v0.x; Vs[lcol + 1][lrow] = v0.y;
        Vs[lcol + 2][lrow] = v0.z; Vs[lcol + 3][lrow] = v0.w;
        Vs[lcol + 0][lrow + 32] = v1.x; Vs[lcol + 1][lrow + 32] = v1.y;
        Vs[lcol + 2][lrow + 32] = v1.z; Vs[lcol + 3][lrow + 32] = v1.w;
        Ws[lcol + 0][lrow] = w0.x; Ws[lcol + 1][lrow] = w0.y;
        Ws[lcol + 2][lrow] = w0.z; Ws[lcol + 3][lrow] = w0.w;
        Ws[lcol + 0][lrow + 32] = w1.x; Ws[lcol + 1][lrow + 32] = w1.y;
        Ws[lcol + 2][lrow + 32] = w1.z; Ws[lcol + 3][lrow + 32] = w1.w;
        __syncthreads();
#pragma unroll
        for (int k = 0; k < 32; k++) {
            float vb[4], wnv[4];
#pragma unroll
            for (int i = 0; i < 4; i++) vb[i] = Vs[k][tb * 4 + i];
#pragma unroll
            for (int j = 0; j < 4; j++) wnv[j] = Ws[k][tn * 4 + j];
#pragma unroll
            for (int i = 0; i < 4; i++)
#pragma unroll
                for (int j = 0; j < 4; j++)
                    acc[i][j] = fmaf(vb[i], wnv[j], acc[i][j]);
        }
    }

    float* out = sel ? g_x : g_p;
#pragma unroll
    for (int i = 0; i < 4; i++)
#pragma unroll
        for (int j = 0; j < 4; j++)
            atomicAdd(&out[(tb * 4 + i) * Hh + nBase + tn * 4 + j], acc[i][j]);
}

// ---------------------------------------------------------------------------
// output[b1,b2,h] = tanh(p[b1,h] + x[b2,h])
// ---------------------------------------------------------------------------
__global__ void output_kernel(float* __restrict__ out) {
    int h = blockIdx.x * 256 + threadIdx.x;
    int b2 = blockIdx.y;
    int b1 = blockIdx.z;
    out[((size_t)b1 * Bb + b2) * Hh + h] =
        tanhf(g_p[b1 * Hh + h] + g_x[b2 * Hh + h]);
}

// ---------------------------------------------------------------------------
// launch
// ---------------------------------------------------------------------------
extern "C" void kernel_launch(void* const* d_in, const int* in_sizes, int n_in,
                              void* d_out, int out_size) {
    (void)in_sizes; (void)n_in; (void)out_size;
    const float* hidden = (const float*)d_in[0];
    // d_in[1] aspect, d_in[4] W_v, d_in[5] b_v, d_in[7] w_b are provably dead
    // (softmax shift-invariance kills the per-batch-constant aspect branch).
    const float* W_h = (const float*)d_in[2];
    const float* b_h = (const float*)d_in[3];
    const float* w_w = (const float*)d_in[6];
    const float* W_p = (const float*)d_in[8];
    const float* b_p = (const float*)d_in[9];
    const float* W_x = (const float*)d_in[10];
    const float* b_x = (const float*)d_in[11];
    float* out = (float*)d_out;

    cudaFuncSetAttribute(gemm_scores_tc,
                         cudaFuncAttributeMaxDynamicSharedMemorySize, SMEM_BYTES);

    __nv_bfloat16* hbf = nullptr;
    __nv_bfloat16* wbf = nullptr;
    cudaGetSymbolAddress((void**)&hbf, g_hbf);
    cudaGetSymbolAddress((void**)&wbf, g_wbf);

    cvt_kernel<<<(Mtot * (Hh / 8)) / 256, 256>>>(hidden, hbf);   // 16384 blocks
    cvt_kernel<<<(Hh * (Hh / 8)) / 256, 256>>>(W_h, wbf);        // 512 blocks
    init_kernel<<<256, 256>>>(b_p, b_x);
    gemm_scores_tc<<<dim3(GX, Mtot / MT), 256, SMEM_BYTES>>>(b_h, w_w);
    softmax_kernel<<<Bb, Tt>>>();
    wsum_kernel<<<dim3(Hh / 256, Bb, 4), 256>>>(hidden);
    small_gemm_kernel<<<dim3(Hh / 64, Hh / 128), 256>>>(hidden, W_p, 0);
    small_gemm_kernel<<<dim3(Hh / 64, Hh / 128), 256>>>(hidden, W_x, 1);
    output_kernel<<<dim3(Hh / 256, Bb, Bb), 256>>>(out);
}

// round 7
// speedup vs baseline: 9.1774x; 1.0155x over previous
#include <cuda_runtime.h>
#include <cuda_bf16.h>
#include <math.h>
#include <stdint.h>

// ---------------------------------------------------------------------------
// Problem constants
// ---------------------------------------------------------------------------
#define Bb 64
#define Tt 512
#define Hh 1024
#define Mtot (Bb * Tt)   // 32768

// Big-GEMM tiling (legacy mma.sync bf16 path — compute_103-safe PTX only)
#define MT 128
#define NT 256
#define KC 64                       // K per smem stage (64 bf16 = 128B rows)
#define NSTG 4
#define KCHUNKS (Hh / KC)           // 16
#define GX (Hh / NT)                // 4
#define A_U32 (MT * KC / 2)         // 4096 uint32 (bf16 pairs)
#define STG_U32 ((MT + NT) * KC / 2)  // 12288 uint32 = 48KB/stage
#define SMEM_U32 (NSTG * STG_U32 + 128)
#define SMEM_BYTES (SMEM_U32 * 4)

// ---------------------------------------------------------------------------
// Scratch (device globals: no allocation allowed)
// ---------------------------------------------------------------------------
__device__ __align__(256) __nv_bfloat16 g_hbf[(size_t)Mtot * Hh];  // 64MB
__device__ __align__(256) __nv_bfloat16 g_wbf[(size_t)Hh * Hh];    // 2MB
__device__ float g_spart[GX * Mtot];   // per-N-tile partial scores
__device__ float g_alpha[Mtot];
__device__ float g_r[Bb * Hh];
__device__ float g_p[Bb * Hh];
__device__ float g_x[Bb * Hh];

// ---------------------------------------------------------------------------
// helpers
// ---------------------------------------------------------------------------
__device__ __forceinline__ uint32_t smem_u32(const void* p) {
    uint32_t a;
    asm("{ .reg .u64 t; cvta.to.shared.u64 t, %1; cvt.u32.u64 %0, t; }" : "=r"(a) : "l"(p));
    return a;
}
__device__ __forceinline__ float tanh_fast(float x) {
    float y;
    asm("tanh.approx.f32 %0, %1;" : "=f"(y) : "f"(x));
    return y;
}
__device__ __forceinline__ uint32_t pack_bf2(float lo, float hi) {
    __nv_bfloat162 v = __float22bfloat162_rn(make_float2(lo, hi));
    return *(uint32_t*)&v;
}

// ---------------------------------------------------------------------------
// fp32 -> bf16 streaming convert (8 elems/thread)
// ---------------------------------------------------------------------------
__global__ void cvt_kernel(const float* __restrict__ s, __nv_bfloat16* __restrict__ d) {
    size_t i = (size_t)blockIdx.x * 256 + threadIdx.x;
    const float4* s4 = (const float4*)s;
    float4 v0 = s4[2 * i], v1 = s4[2 * i + 1];
    uint4 o;
    o.x = pack_bf2(v0.x, v0.y);
    o.y = pack_bf2(v0.z, v0.w);
    o.z = pack_bf2(v1.x, v1.y);
    o.w = pack_bf2(v1.z, v1.w);
    ((uint4*)d)[i] = o;
}

// ---------------------------------------------------------------------------
// init: zero r accumulator, preload biases into p/x accumulators
// ---------------------------------------------------------------------------
__global__ void init_kernel(const float* __restrict__ b_p,
                            const float* __restrict__ b_x) {
    int i = blockIdx.x * 256 + threadIdx.x;   // 65536 threads
    g_r[i] = 0.f;
    g_p[i] = b_p[i & (Hh - 1)];
    g_x[i] = b_x[i & (Hh - 1)];
}

// ---------------------------------------------------------------------------
// Big GEMM (M=32768,N=1024,K=1024) on mma.sync m16n8k16 bf16, fused
// tanh*w_w score-reduction epilogue. CTA tile 128x256, 8 warps (64x64 each),
// 4-stage cp.async pipeline with LDGSTS issue interleaved between MMA
// k-steps (keeps tensor queue fed), XOR-swizzled conflict-free smem.
// ---------------------------------------------------------------------------
__global__ __launch_bounds__(256, 1)
void gemm_scores_tc(const float* __restrict__ bh,
                    const float* __restrict__ ww) {
    extern __shared__ uint32_t sm[];
    float* s_red = (float*)(sm + NSTG * STG_U32);

    int tid = threadIdx.x;
    int w = tid >> 5, lane = tid & 31;
    int gid = lane >> 2, tig = lane & 3;
    int wm = (w >> 2) * 64;         // 0 / 64
    int wn = (w & 3) * 64;          // 0..192
    int m0 = blockIdx.y * MT;
    int n0 = blockIdx.x * NT;

    if (tid < 128) s_red[tid] = 0.f;

    uint32_t sbase = smem_u32(sm);
    const char* Ab = (const char*)(g_hbf + (size_t)m0 * Hh);
    const char* Wb = (const char*)(g_wbf + (size_t)n0 * Hh);

    // A-half of a stage fill: 4 x cp.async(16B) per thread
    auto issue_a = [&](int s, int kidx) {
        uint32_t aS = sbase + s * (STG_U32 * 4);
        int kb = kidx * (KC * 2);
#pragma unroll
        for (int u = 0; u < 4; u++) {
            int c = tid + u * 256;
            int row = c >> 3, ch = c & 7;
            const char* g = Ab + (size_t)row * (Hh * 2) + kb + ch * 16;
            uint32_t d = aS + row * 128 + ((ch ^ (row & 7)) * 16);
            asm volatile("cp.async.cg.shared.global [%0], [%1], 16;" :: "r"(d), "l"(g));
        }
    };
    // B-half + commit: 8 x cp.async(16B) per thread
    auto issue_b = [&](int s, int kidx) {
        uint32_t bS = sbase + s * (STG_U32 * 4) + A_U32 * 4;
        int kb = kidx * (KC * 2);
#pragma unroll
        for (int u = 0; u < 8; u++) {
            int c = tid + u * 256;
            int row = c >> 3, ch = c & 7;
            const char* g = Wb + (size_t)row * (Hh * 2) + kb + ch * 16;
            uint32_t d = bS + row * 128 + ((ch ^ (row & 7)) * 16);
            asm volatile("cp.async.cg.shared.global [%0], [%1], 16;" :: "r"(d), "l"(g));
        }
        asm volatile("cp.async.commit_group;" ::: "memory");
    };

    issue_a(0, 0); issue_b(0, 0);
    issue_a(1, 1); issue_b(1, 1);
    issue_a(2, 2); issue_b(2, 2);

    float acc[4][8][4];
#pragma unroll
    for (int i = 0; i < 4; i++)
#pragma unroll
        for (int j = 0; j < 8; j++)
#pragma unroll
            for (int r = 0; r < 4; r++) acc[i][j][r] = 0.f;

    int aOff[4], bOff[8];
#pragma unroll
    for (int i = 0; i < 4; i++) aOff[i] = (wm + i * 16 + gid) * 32 + tig;
#pragma unroll
    for (int j = 0; j < 8; j++) bOff[j] = (wn + j * 8 + gid) * 32 + tig;

    // one K=16 MMA step over all warp fragments
    auto kstep = [&](const uint32_t* Sa, const uint32_t* Sb, int kk) {
        int sw0 = ((2 * kk) ^ gid) * 4;
        int sw1 = ((2 * kk + 1) ^ gid) * 4;
        uint32_t af[4][4];
#pragma unroll
        for (int i = 0; i < 4; i++) {
            af[i][0] = Sa[aOff[i] + sw0];
            af[i][1] = Sa[aOff[i] + 256 + sw0];
            af[i][2] = Sa[aOff[i] + sw1];
            af[i][3] = Sa[aOff[i] + 256 + sw1];
        }
        uint32_t bfr[8][2];
#pragma unroll
        for (int j = 0; j < 8; j++) {
            bfr[j][0] = Sb[bOff[j] + sw0];
            bfr[j][1] = Sb[bOff[j] + sw1];
        }
#pragma unroll
        for (int i = 0; i < 4; i++)
#pragma unroll
            for (int j = 0; j < 8; j++)
                asm volatile(
                    "mma.sync.aligned.m16n8k16.row.col.f32.bf16.bf16.f32 "
                    "{%0,%1,%2,%3}, {%4,%5,%6,%7}, {%8,%9}, {%0,%1,%2,%3};"
                    : "+f"(acc[i][j][0]), "+f"(acc[i][j][1]),
                      "+f"(acc[i][j][2]), "+f"(acc[i][j][3])
                    : "r"(af[i][0]), "r"(af[i][1]), "r"(af[i][2]), "r"(af[i][3]),
                      "r"(bfr[j][0]), "r"(bfr[j][1]));
    };

    for (int ks = 0; ks < KCHUNKS; ks++) {
        if (ks <= KCHUNKS - 3)
            asm volatile("cp.async.wait_group 2;" ::: "memory");
        else if (ks == KCHUNKS - 2)
            asm volatile("cp.async.wait_group 1;" ::: "memory");
        else
            asm volatile("cp.async.wait_group 0;" ::: "memory");
        __syncthreads();

        const uint32_t* Sa = sm + (ks & 3) * STG_U32;
        const uint32_t* Sb = Sa + A_U32;
        bool pf = (ks + 3 < KCHUNKS);

        kstep(Sa, Sb, 0);
        if (pf) issue_a((ks + 3) & 3, ks + 3);   // interleave LDGSTS with MMA
        kstep(Sa, Sb, 1);
        if (pf) issue_b((ks + 3) & 3, ks + 3);
        kstep(Sa, Sb, 2);
        kstep(Sa, Sb, 3);
    }

    // Fused epilogue: part[m] = sum_n tanh(acc + bh[n]) * ww[n]
    float bhv[8][2], wwv[8][2];
#pragma unroll
    for (int j = 0; j < 8; j++) {
#pragma unroll
        for (int h = 0; h < 2; h++) {
            int n = n0 + wn + j * 8 + 2 * tig + h;
            bhv[j][h] = bh[n];
            wwv[j][h] = ww[n];
        }
    }
#pragma unroll
    for (int i = 0; i < 4; i++) {
        float p0 = 0.f, p1 = 0.f;
#pragma unroll
        for (int j = 0; j < 8; j++) {
            p0 += tanh_fast(acc[i][j][0] + bhv[j][0]) * wwv[j][0];
            p0 += tanh_fast(acc[i][j][1] + bhv[j][1]) * wwv[j][1];
            p1 += tanh_fast(acc[i][j][2] + bhv[j][0]) * wwv[j][0];
            p1 += tanh_fast(acc[i][j][3] + bhv[j][1]) * wwv[j][1];
        }
        p0 += __shfl_xor_sync(0xffffffffu, p0, 1);
        p0 += __shfl_xor_sync(0xffffffffu, p0, 2);
        p1 += __shfl_xor_sync(0xffffffffu, p1, 1);
        p1 += __shfl_xor_sync(0xffffffffu, p1, 2);
        if (tig == 0) {
            atomicAdd(&s_red[wm + i * 16 + gid], p0);
            atomicAdd(&s_red[wm + i * 16 + gid + 8], p1);
        }
    }
    __syncthreads();
    if (tid < 128)
        g_spart[blockIdx.x * Mtot + m0 + tid] = s_red[tid];
}

// ---------------------------------------------------------------------------
// softmax over T per batch row (sums the GX partial-score slabs)
// ---------------------------------------------------------------------------
__global__ void softmax_kernel() {
    __shared__ float red[Tt];
    int b = blockIdx.x;
    int t = threadIdx.x;
    float s = 0.f;
#pragma unroll
    for (int p = 0; p < GX; p++) s += g_spart[p * Mtot + b * Tt + t];
    red[t] = s;
    __syncthreads();
    for (int off = 256; off > 0; off >>= 1) {
        if (t < off) red[t] = fmaxf(red[t], red[t + off]);
        __syncthreads();
    }
    float mx = red[0];
    __syncthreads();
    float e = expf(s - mx);
    red[t] = e;
    __syncthreads();
    for (int off = 256; off > 0; off >>= 1) {
        if (t < off) red[t] += red[t + off];
        __syncthreads();
    }
    g_alpha[b * Tt + t] = e / red[0];
}

// ---------------------------------------------------------------------------
// r[b,h] += sum_t alpha[b,t]*hidden[b,t,h] — reads bf16 copy (half traffic),
// each thread covers an h-pair; T split 4 ways for MLP.
// ---------------------------------------------------------------------------
__global__ void wsum_kernel() {
    __shared__ float a_s[128];
    int seg = blockIdx.z;
    int b = blockIdx.y;
    int h2 = blockIdx.x * 256 + threadIdx.x;       // bf16x2 index, 0..511
    if (threadIdx.x < 128) a_s[threadIdx.x] = g_alpha[b * Tt + seg * 128 + threadIdx.x];
    __syncthreads();
    const __nv_bfloat162* hp = (const __nv_bfloat162*)g_hbf
        + ((size_t)b * Tt + seg * 128) * (Hh / 2) + h2;
    float ax[4], ay[4];
#pragma unroll
    for (int u = 0; u < 4; u++) { ax[u] = 0.f; ay[u] = 0.f; }
    for (int t = 0; t < 128; t += 4) {
#pragma unroll
        for (int u = 0; u < 4; u++) {
            float2 v = __bfloat1622float2(hp[(size_t)(t + u) * (Hh / 2)]);
            float a = a_s[t + u];
            ax[u] = fmaf(a, v.x, ax[u]);
            ay[u] = fmaf(a, v.y, ay[u]);
        }
    }
    atomicAdd(&g_r[b * Hh + 2 * h2],     (ax[0] + ax[1]) + (ax[2] + ax[3]));
    atomicAdd(&g_r[b * Hh + 2 * h2 + 1], (ay[0] + ay[1]) + (ay[2] + ay[3]));
}

// ---------------------------------------------------------------------------
// small GEMM: out[b,n] += V[b,:] . W[n,:]   (out pre-initialized with bias)
// blockIdx.z selects the p-path (r@W_p) or x-path (hidden_last@W_x).
// ---------------------------------------------------------------------------
__global__ __launch_bounds__(256)
void small_gemm_kernel(const float* __restrict__ hidden,
                       const float* __restrict__ W_p,
                       const float* __restrict__ W_x) {
    __shared__ float Vs[32][68];
    __shared__ float Ws[32][68];

    int sel = blockIdx.z;
    const float* W = sel ? W_x : W_p;
    const float* V;
    size_t vstride;
    if (sel) { V = hidden + (size_t)(Tt - 1) * Hh; vstride = (size_t)Tt * Hh; }
    else     { V = g_r; vstride = Hh; }

    int tid = threadIdx.x;
    int nBase = blockIdx.x * 64;
    int kBase = blockIdx.y * 128;

    int tn = tid & 15;
    int tb = tid >> 4;
    int lrow = tid >> 3;
    int lcol = (tid & 7) << 2;

    float acc[4][4];
#pragma unroll
    for (int i = 0; i < 4; i++)
#pragma unroll
        for (int j = 0; j < 4; j++) acc[i][j] = 0.f;

    for (int kc = 0; kc < 128; kc += 32) {
        int kg = kBase + kc;
        float4 v0 = *(const float4*)(V + (size_t)lrow * vstride + kg + lcol);
        float4 v1 = *(const float4*)(V + (size_t)(lrow + 32) * vstride + kg + lcol);
        float4 w0 = *(const float4*)(W + (size_t)(nBase + lrow) * Hh + kg + lcol);
        float4 w1 = *(const float4*)(W + (size_t)(nBase + lrow + 32) * Hh + kg + lcol);
        __syncthreads();
        Vs[lcol + 0][lrow] = v0.x; Vs[lcol + 1][lrow] = v0.y;
        Vs[lcol + 2][lrow] = v0.z; Vs[lcol + 3][lrow] = v0.w;
        Vs[lcol + 0][lrow + 32] = v1.x; Vs[lcol + 1][lrow + 32] = v1.y;
        Vs[lcol + 2][lrow + 32] = v1.z; Vs[lcol + 3][lrow + 32] = v1.w;
        Ws[lcol + 0][lrow] = w0.x; Ws[lcol + 1][lrow] = w0.y;
        Ws[lcol + 2][lrow] = w0.z; Ws[lcol + 3][lrow] = w0.w;
        Ws[lcol + 0][lrow + 32] = w1.x; Ws[lcol + 1][lrow + 32] = w1.y;
        Ws[lcol + 2][lrow + 32] = w1.z; Ws[lcol + 3][lrow + 32] = w1.w;
        __syncthreads();
#pragma unroll
        for (int k = 0; k < 32; k++) {
            float vb[4], wnv[4];
#pragma unroll
            for (int i = 0; i < 4; i++) vb[i] = Vs[k][tb * 4 + i];
#pragma unroll
            for (int j = 0; j < 4; j++) wnv[j] = Ws[k][tn * 4 + j];
#pragma unroll
            for (int i = 0; i < 4; i++)
#pragma unroll
                for (int j = 0; j < 4; j++)
                    acc[i][j] = fmaf(vb[i], wnv[j], acc[i][j]);
        }
    }

    float* out = sel ? g_x : g_p;
#pragma unroll
    for (int i = 0; i < 4; i++)
#pragma unroll
        for (int j = 0; j < 4; j++)
            atomicAdd(&out[(tb * 4 + i) * Hh + nBase + tn * 4 + j], acc[i][j]);
}

// ---------------------------------------------------------------------------
// output[b1,b2,h] = tanh(p[b1,h] + x[b2,h])
// ---------------------------------------------------------------------------
__global__ void output_kernel(float* __restrict__ out) {
    int h = blockIdx.x * 256 + threadIdx.x;
    int b2 = blockIdx.y;
    int b1 = blockIdx.z;
    out[((size_t)b1 * Bb + b2) * Hh + h] =
        tanhf(g_p[b1 * Hh + h] + g_x[b2 * Hh + h]);
}

// ---------------------------------------------------------------------------
// launch
// ---------------------------------------------------------------------------
extern "C" void kernel_launch(void* const* d_in, const int* in_sizes, int n_in,
                              void* d_out, int out_size) {
    (void)in_sizes; (void)n_in; (void)out_size;
    const float* hidden = (const float*)d_in[0];
    // d_in[1] aspect, d_in[4] W_v, d_in[5] b_v, d_in[7] w_b are provably dead
    // (softmax shift-invariance kills the per-batch-constant aspect branch).
    const float* W_h = (const float*)d_in[2];
    const float* b_h = (const float*)d_in[3];
    const float* w_w = (const float*)d_in[6];
    const float* W_p = (const float*)d_in[8];
    const float* b_p = (const float*)d_in[9];
    const float* W_x = (const float*)d_in[10];
    const float* b_x = (const float*)d_in[11];
    float* out = (float*)d_out;

    cudaFuncSetAttribute(gemm_scores_tc,
                         cudaFuncAttributeMaxDynamicSharedMemorySize, SMEM_BYTES);

    __nv_bfloat16* hbf = nullptr;
    __nv_bfloat16* wbf = nullptr;
    cudaGetSymbolAddress((void**)&hbf, g_hbf);
    cudaGetSymbolAddress((void**)&wbf, g_wbf);

    cvt_kernel<<<(Mtot * (Hh / 8)) / 256, 256>>>(hidden, hbf);   // 16384 blocks
    cvt_kernel<<<(Hh * (Hh / 8)) / 256, 256>>>(W_h, wbf);        // 512 blocks
    init_kernel<<<256, 256>>>(b_p, b_x);
    gemm_scores_tc<<<dim3(GX, Mtot / MT), 256, SMEM_BYTES>>>(b_h, w_w);
    softmax_kernel<<<Bb, Tt>>>();
    wsum_kernel<<<dim3(Hh / 512, Bb, 4), 256>>>();
    small_gemm_kernel<<<dim3(Hh / 64, Hh / 128, 2), 256>>>(hidden, W_p, W_x);
    output_kernel<<<dim3(Hh / 256, Bb, Bb), 256>>>(out);
}

// round 8
// speedup vs baseline: 10.2750x; 1.1196x over previous
#include <cuda_runtime.h>
#include <cuda_bf16.h>
#include <math.h>
#include <stdint.h>

// ---------------------------------------------------------------------------
// Problem constants
// ---------------------------------------------------------------------------
#define Bb 64
#define Tt 512
#define Hh 1024
#define Mtot (Bb * Tt)   // 32768

// Big-GEMM tiling: CTA 128x128, 4 warps (64x64 each), 2 CTAs/SM
#define MT 128
#define NT 128
#define KC 64                        // K per smem stage (64 bf16 = 128B rows)
#define NSTG 3
#define KCHUNKS (Hh / KC)            // 16
#define GX (Hh / NT)                 // 8
#define A_U32 (MT * KC / 2)          // 4096 uint32 (bf16 pairs)
#define STG_U32 ((MT + NT) * KC / 2) // 8192 uint32 = 32KB/stage
#define SMEM_U32 (NSTG * STG_U32 + 128)
#define SMEM_BYTES (SMEM_U32 * 4)    // 98816

// ---------------------------------------------------------------------------
// Scratch (device globals: no allocation allowed)
// ---------------------------------------------------------------------------
__device__ __align__(256) __nv_bfloat16 g_hbf[(size_t)Mtot * Hh];  // 64MB
__device__ __align__(256) __nv_bfloat16 g_wbf[(size_t)Hh * Hh];    // 2MB
__device__ float g_spart[GX * Mtot];   // per-N-tile partial scores (1MB)
__device__ float g_alpha[Mtot];
__device__ float g_r[Bb * Hh];
__device__ float g_p[Bb * Hh];
__device__ float g_x[Bb * Hh];

// ---------------------------------------------------------------------------
// helpers
// ---------------------------------------------------------------------------
__device__ __forceinline__ uint32_t smem_u32(const void* p) {
    uint32_t a;
    asm("{ .reg .u64 t; cvta.to.shared.u64 t, %1; cvt.u32.u64 %0, t; }" : "=r"(a) : "l"(p));
    return a;
}
__device__ __forceinline__ float tanh_fast(float x) {
    float y;
    asm("tanh.approx.f32 %0, %1;" : "=f"(y) : "f"(x));
    return y;
}
__device__ __forceinline__ uint32_t pack_bf2(float lo, float hi) {
    __nv_bfloat162 v = __float22bfloat162_rn(make_float2(lo, hi));
    return *(uint32_t*)&v;
}

// ---------------------------------------------------------------------------
// fp32 -> bf16 streaming convert (8 elems/thread)
// ---------------------------------------------------------------------------
__global__ void cvt_kernel(const float* __restrict__ s, __nv_bfloat16* __restrict__ d) {
    size_t i = (size_t)blockIdx.x * 256 + threadIdx.x;
    const float4* s4 = (const float4*)s;
    float4 v0 = s4[2 * i], v1 = s4[2 * i + 1];
    uint4 o;
    o.x = pack_bf2(v0.x, v0.y);
    o.y = pack_bf2(v0.z, v0.w);
    o.z = pack_bf2(v1.x, v1.y);
    o.w = pack_bf2(v1.z, v1.w);
    ((uint4*)d)[i] = o;
}

// ---------------------------------------------------------------------------
// init: zero r accumulator, preload biases into p/x accumulators
// ---------------------------------------------------------------------------
__global__ void init_kernel(const float* __restrict__ b_p,
                            const float* __restrict__ b_x) {
    int i = blockIdx.x * 256 + threadIdx.x;   // 65536 threads
    g_r[i] = 0.f;
    g_p[i] = b_p[i & (Hh - 1)];
    g_x[i] = b_x[i & (Hh - 1)];
}

// ---------------------------------------------------------------------------
// Big GEMM (M=32768,N=1024,K=1024) on mma.sync m16n8k16 bf16, fused
// tanh*w_w score-reduction epilogue. CTA tile 128x128, 4 warps (64x64),
// 3-stage cp.async pipeline, 2 CTAs/SM so barriers/fill bursts of one CTA
// overlap the other CTA's HMMA stream. XOR-swizzled conflict-free smem.
// ---------------------------------------------------------------------------
__global__ __launch_bounds__(128, 2)
void gemm_scores_tc(const float* __restrict__ bh,
                    const float* __restrict__ ww) {
    extern __shared__ uint32_t sm[];
    float* s_red = (float*)(sm + NSTG * STG_U32);

    int tid = threadIdx.x;
    int w = tid >> 5, lane = tid & 31;
    int gid = lane >> 2, tig = lane & 3;
    int wm = (w >> 1) * 64;         // 0 / 64
    int wn = (w & 1) * 64;          // 0 / 64
    int m0 = blockIdx.y * MT;
    int n0 = blockIdx.x * NT;

    s_red[tid] = 0.f;

    uint32_t sbase = smem_u32(sm);
    const char* Ab = (const char*)(g_hbf + (size_t)m0 * Hh);
    const char* Wb = (const char*)(g_wbf + (size_t)n0 * Hh);

    // full stage fill: 16 x cp.async(16B) per thread (A 8 + B 8)
    auto issue = [&](int s, int kidx) {
        uint32_t aS = sbase + s * (STG_U32 * 4);
        uint32_t bS = aS + A_U32 * 4;
        int kb = kidx * (KC * 2);
#pragma unroll
        for (int u = 0; u < 8; u++) {            // A: 1024 chunks of 16B
            int c = tid + u * 128;
            int row = c >> 3, ch = c & 7;
            const char* g = Ab + (size_t)row * (Hh * 2) + kb + ch * 16;
            uint32_t d = aS + row * 128 + ((ch ^ (row & 7)) * 16);
            asm volatile("cp.async.cg.shared.global [%0], [%1], 16;" :: "r"(d), "l"(g));
        }
#pragma unroll
        for (int u = 0; u < 8; u++) {            // B: 1024 chunks
            int c = tid + u * 128;
            int row = c >> 3, ch = c & 7;
            const char* g = Wb + (size_t)row * (Hh * 2) + kb + ch * 16;
            uint32_t d = bS + row * 128 + ((ch ^ (row & 7)) * 16);
            asm volatile("cp.async.cg.shared.global [%0], [%1], 16;" :: "r"(d), "l"(g));
        }
        asm volatile("cp.async.commit_group;" ::: "memory");
    };

    issue(0, 0); issue(1, 1);

    float acc[4][8][4];
#pragma unroll
    for (int i = 0; i < 4; i++)
#pragma unroll
        for (int j = 0; j < 8; j++)
#pragma unroll
            for (int r = 0; r < 4; r++) acc[i][j][r] = 0.f;

    int aOff[4], bOff[8];
#pragma unroll
    for (int i = 0; i < 4; i++) aOff[i] = (wm + i * 16 + gid) * 32 + tig;
#pragma unroll
    for (int j = 0; j < 8; j++) bOff[j] = (wn + j * 8 + gid) * 32 + tig;

    for (int ks = 0; ks < KCHUNKS; ks++) {
        if (ks < KCHUNKS - 1)
            asm volatile("cp.async.wait_group 1;" ::: "memory");
        else
            asm volatile("cp.async.wait_group 0;" ::: "memory");
        __syncthreads();
        if (ks + 2 < KCHUNKS) issue((ks + 2) % NSTG, ks + 2);

        const uint32_t* Sa = sm + (ks % NSTG) * STG_U32;
        const uint32_t* Sb = Sa + A_U32;
#pragma unroll
        for (int kk = 0; kk < 4; kk++) {
            int sw0 = ((2 * kk) ^ gid) * 4;
            int sw1 = ((2 * kk + 1) ^ gid) * 4;
            uint32_t af[4][4];
#pragma unroll
            for (int i = 0; i < 4; i++) {
                af[i][0] = Sa[aOff[i] + sw0];
                af[i][1] = Sa[aOff[i] + 256 + sw0];
                af[i][2] = Sa[aOff[i] + sw1];
                af[i][3] = Sa[aOff[i] + 256 + sw1];
            }
            uint32_t bfr[8][2];
#pragma unroll
            for (int j = 0; j < 8; j++) {
                bfr[j][0] = Sb[bOff[j] + sw0];
                bfr[j][1] = Sb[bOff[j] + sw1];
            }
#pragma unroll
            for (int i = 0; i < 4; i++)
#pragma unroll
                for (int j = 0; j < 8; j++)
                    asm volatile(
                        "mma.sync.aligned.m16n8k16.row.col.f32.bf16.bf16.f32 "
                        "{%0,%1,%2,%3}, {%4,%5,%6,%7}, {%8,%9}, {%0,%1,%2,%3};"
                        : "+f"(acc[i][j][0]), "+f"(acc[i][j][1]),
                          "+f"(acc[i][j][2]), "+f"(acc[i][j][3])
                        : "r"(af[i][0]), "r"(af[i][1]), "r"(af[i][2]), "r"(af[i][3]),
                          "r"(bfr[j][0]), "r"(bfr[j][1]));
        }
    }

    // Fused epilogue: part[m] = sum_n tanh(acc + bh[n]) * ww[n]
    float bhv[8][2], wwv[8][2];
#pragma unroll
    for (int j = 0; j < 8; j++) {
#pragma unroll
        for (int h = 0; h < 2; h++) {
            int n = n0 + wn + j * 8 + 2 * tig + h;
            bhv[j][h] = bh[n];
            wwv[j][h] = ww[n];
        }
    }
#pragma unroll
    for (int i = 0; i < 4; i++) {
        float p0 = 0.f, p1 = 0.f;
#pragma unroll
        for (int j = 0; j < 8; j++) {
            p0 += tanh_fast(acc[i][j][0] + bhv[j][0]) * wwv[j][0];
            p0 += tanh_fast(acc[i][j][1] + bhv[j][1]) * wwv[j][1];
            p1 += tanh_fast(acc[i][j][2] + bhv[j][0]) * wwv[j][0];
            p1 += tanh_fast(acc[i][j][3] + bhv[j][1]) * wwv[j][1];
        }
        p0 += __shfl_xor_sync(0xffffffffu, p0, 1);
        p0 += __shfl_xor_sync(0xffffffffu, p0, 2);
        p1 += __shfl_xor_sync(0xffffffffu, p1, 1);
        p1 += __shfl_xor_sync(0xffffffffu, p1, 2);
        if (tig == 0) {
            atomicAdd(&s_red[wm + i * 16 + gid], p0);
            atomicAdd(&s_red[wm + i * 16 + gid + 8], p1);
        }
    }
    __syncthreads();
    g_spart[blockIdx.x * Mtot + m0 + tid] = s_red[tid];
}

// ---------------------------------------------------------------------------
// softmax over T per batch row (sums the GX partial-score slabs)
// ---------------------------------------------------------------------------
__global__ void softmax_kernel() {
    __shared__ float red[Tt];
    int b = blockIdx.x;
    int t = threadIdx.x;
    float s = 0.f;
#pragma unroll
    for (int p = 0; p < GX; p++) s += g_spart[p * Mtot + b * Tt + t];
    red[t] = s;
    __syncthreads();
    for (int off = 256; off > 0; off >>= 1) {
        if (t < off) red[t] = fmaxf(red[t], red[t + off]);
        __syncthreads();
    }
    float mx = red[0];
    __syncthreads();
    float e = expf(s - mx);
    red[t] = e;
    __syncthreads();
    for (int off = 256; off > 0; off >>= 1) {
        if (t < off) red[t] += red[t + off];
        __syncthreads();
    }
    g_alpha[b * Tt + t] = e / red[0];
}

// ---------------------------------------------------------------------------
// r[b,h] += sum_t alpha[b,t]*hidden[b,t,h] — reads bf16 copy (half traffic),
// each thread covers an h-pair; T split 4 ways for MLP.
// ---------------------------------------------------------------------------
__global__ void wsum_kernel() {
    __shared__ float a_s[128];
    int seg = blockIdx.z;
    int b = blockIdx.y;
    int h2 = blockIdx.x * 256 + threadIdx.x;       // bf16x2 index, 0..511
    if (threadIdx.x < 128) a_s[threadIdx.x] = g_alpha[b * Tt + seg * 128 + threadIdx.x];
    __syncthreads();
    const __nv_bfloat162* hp = (const __nv_bfloat162*)g_hbf
        + ((size_t)b * Tt + seg * 128) * (Hh / 2) + h2;
    float ax[4], ay[4];
#pragma unroll
    for (int u = 0; u < 4; u++) { ax[u] = 0.f; ay[u] = 0.f; }
    for (int t = 0; t < 128; t += 4) {
#pragma unroll
        for (int u = 0; u < 4; u++) {
            float2 v = __bfloat1622float2(hp[(size_t)(t + u) * (Hh / 2)]);
            float a = a_s[t + u];
            ax[u] = fmaf(a, v.x, ax[u]);
            ay[u] = fmaf(a, v.y, ay[u]);
        }
    }
    atomicAdd(&g_r[b * Hh + 2 * h2],     (ax[0] + ax[1]) + (ax[2] + ax[3]));
    atomicAdd(&g_r[b * Hh + 2 * h2 + 1], (ay[0] + ay[1]) + (ay[2] + ay[3]));
}

// ---------------------------------------------------------------------------
// small GEMM: out[b,n] += V[b,:] . W[n,:]   (out pre-initialized with bias)
// blockIdx.z selects the p-path (r@W_p) or x-path (hidden_last@W_x).
// ---------------------------------------------------------------------------
__global__ __launch_bounds__(256)
void small_gemm_kernel(const float* __restrict__ hidden,
                       const float* __restrict__ W_p,
                       const float* __restrict__ W_x) {
    __shared__ float Vs[32][68];
    __shared__ float Ws[32][68];

    int sel = blockIdx.z;
    const float* W = sel ? W_x : W_p;
    const float* V;
    size_t vstride;
    if (sel) { V = hidden + (size_t)(Tt - 1) * Hh; vstride = (size_t)Tt * Hh; }
    else     { V = g_r; vstride = Hh; }

    int tid = threadIdx.x;
    int nBase = blockIdx.x * 64;
    int kBase = blockIdx.y * 128;

    int tn = tid & 15;
    int tb = tid >> 4;
    int lrow = tid >> 3;
    int lcol = (tid & 7) << 2;

    float acc[4][4];
#pragma unroll
    for (int i = 0; i < 4; i++)
#pragma unroll
        for (int j = 0; j < 4; j++) acc[i][j] = 0.f;

    for (int kc = 0; kc < 128; kc += 32) {
        int kg = kBase + kc;
        float4 v0 = *(const float4*)(V + (size_t)lrow * vstride + kg + lcol);
        float4 v1 = *(const float4*)(V + (size_t)(lrow + 32) * vstride + kg + lcol);
        float4 w0 = *(const float4*)(W + (size_t)(nBase + lrow) * Hh + kg + lcol);
        float4 w1 = *(const float4*)(W + (size_t)(nBase + lrow + 32) * Hh + kg + lcol);
        __syncthreads();
        Vs[lcol + 0][lrow] = v0.x; Vs[lcol + 1][lrow] = v0.y;
        Vs[lcol + 2][lrow] = v0.z; Vs[lcol + 3][lrow] = v0.w;
        Vs[lcol + 0][lrow + 32] = v1.x; Vs[lcol + 1][lrow + 32] = v1.y;
        Vs[lcol + 2][lrow + 32] = v1.z; Vs[lcol + 3][lrow + 32] = v1.w;
        Ws[lcol + 0][lrow] = w0.x; Ws[lcol + 1][lrow] = w0.y;
        Ws[lcol + 2][lrow] = w0.z; Ws[lcol + 3][lrow] = w0.w;
        Ws[lcol + 0][lrow + 32] = w1.x; Ws[lcol + 1][lrow + 32] = w1.y;
        Ws[lcol + 2][lrow + 32] = w1.z; Ws[lcol + 3][lrow + 32] = w1.w;
        __syncthreads();
#pragma unroll
        for (int k = 0; k < 32; k++) {
            float vb[4], wnv[4];
#pragma unroll
            for (int i = 0; i < 4; i++) vb[i] = Vs[k][tb * 4 + i];
#pragma unroll
            for (int j = 0; j < 4; j++) wnv[j] = Ws[k][tn * 4 + j];
#pragma unroll
            for (int i = 0; i < 4; i++)
#pragma unroll
                for (int j = 0; j < 4; j++)
                    acc[i][j] = fmaf(vb[i], wnv[j], acc[i][j]);
        }
    }

    float* out = sel ? g_x : g_p;
#pragma unroll
    for (int i = 0; i < 4; i++)
#pragma unroll
        for (int j = 0; j < 4; j++)
            atomicAdd(&out[(tb * 4 + i) * Hh + nBase + tn * 4 + j], acc[i][j]);
}

// ---------------------------------------------------------------------------
// output[b1,b2,h] = tanh(p[b1,h] + x[b2,h])
// ---------------------------------------------------------------------------
__global__ void output_kernel(float* __restrict__ out) {
    int h = blockIdx.x * 256 + threadIdx.x;
    int b2 = blockIdx.y;
    int b1 = blockIdx.z;
    out[((size_t)b1 * Bb + b2) * Hh + h] =
        tanhf(g_p[b1 * Hh + h] + g_x[b2 * Hh + h]);
}

// ---------------------------------------------------------------------------
// launch
// ---------------------------------------------------------------------------
extern "C" void kernel_launch(void* const* d_in, const int* in_sizes, int n_in,
                              void* d_out, int out_size) {
    (void)in_sizes; (void)n_in; (void)out_size;
    const float* hidden = (const float*)d_in[0];
    // d_in[1] aspect, d_in[4] W_v, d_in[5] b_v, d_in[7] w_b are provably dead
    // (softmax shift-invariance kills the per-batch-constant aspect branch).
    const float* W_h = (const float*)d_in[2];
    const float* b_h = (const float*)d_in[3];
    const float* w_w = (const float*)d_in[6];
    const float* W_p = (const float*)d_in[8];
    const float* b_p = (const float*)d_in[9];
    const float* W_x = (const float*)d_in[10];
    const float* b_x = (const float*)d_in[11];
    float* out = (float*)d_out;

    cudaFuncSetAttribute(gemm_scores_tc,
                         cudaFuncAttributeMaxDynamicSharedMemorySize, SMEM_BYTES);

    __nv_bfloat16* hbf = nullptr;
    __nv_bfloat16* wbf = nullptr;
    cudaGetSymbolAddress((void**)&hbf, g_hbf);
    cudaGetSymbolAddress((void**)&wbf, g_wbf);

    cvt_kernel<<<(Mtot * (Hh / 8)) / 256, 256>>>(hidden, hbf);   // 16384 blocks
    cvt_kernel<<<(Hh * (Hh / 8)) / 256, 256>>>(W_h, wbf);        // 512 blocks
    init_kernel<<<256, 256>>>(b_p, b_x);
    gemm_scores_tc<<<dim3(GX, Mtot / MT), 128, SMEM_BYTES>>>(b_h, w_w);
    softmax_kernel<<<Bb, Tt>>>();
    wsum_kernel<<<dim3(Hh / 512, Bb, 4), 256>>>();
    small_gemm_kernel<<<dim3(Hh / 64, Hh / 128, 2), 256>>>(hidden, W_p, W_x);
    output_kernel<<<dim3(Hh / 256, Bb, Bb), 256>>>(out);
}

// round 9
// speedup vs baseline: 10.5643x; 1.0282x over previous
#include <cuda_runtime.h>
#include <cuda_bf16.h>
#include <math.h>
#include <stdint.h>

// ---------------------------------------------------------------------------
// Problem constants
// ---------------------------------------------------------------------------
#define Bb 64
#define Tt 512
#define Hh 1024
#define Mtot (Bb * Tt)   // 32768

// Big-GEMM tiling: CTA 128x128, 4 warps (64x64 each), 2 CTAs/SM
#define MT 128
#define NT 128
#define KC 64                        // K per smem stage (64 bf16 = 128B rows)
#define NSTG 3
#define KCHUNKS (Hh / KC)            // 16
#define GX (Hh / NT)                 // 8
#define A_U32 (MT * KC / 2)          // 4096 uint32 (bf16 pairs)
#define STG_U32 ((MT + NT) * KC / 2) // 8192 uint32 = 32KB/stage
#define SMEM_U32 (NSTG * STG_U32 + 128)
#define SMEM_BYTES (SMEM_U32 * 4)    // 98816

// ---------------------------------------------------------------------------
// Scratch (device globals: no allocation allowed)
// ---------------------------------------------------------------------------
__device__ __align__(256) __nv_bfloat16 g_hbf[(size_t)Mtot * Hh];  // 64MB
__device__ __align__(256) __nv_bfloat16 g_wbf[(size_t)Hh * Hh];    // 2MB
__device__ float g_spart[GX * Mtot];   // per-N-tile partial scores (1MB)
__device__ float g_alpha[Mtot];
__device__ float g_r[Bb * Hh];
__device__ float g_p[Bb * Hh];
__device__ float g_x[Bb * Hh];

// ---------------------------------------------------------------------------
// helpers
// ---------------------------------------------------------------------------
__device__ __forceinline__ uint32_t smem_u32(const void* p) {
    uint32_t a;
    asm("{ .reg .u64 t; cvta.to.shared.u64 t, %1; cvt.u32.u64 %0, t; }" : "=r"(a) : "l"(p));
    return a;
}
__device__ __forceinline__ float tanh_fast(float x) {
    float y;
    asm("tanh.approx.f32 %0, %1;" : "=f"(y) : "f"(x));
    return y;
}
__device__ __forceinline__ uint32_t pack_bf2(float lo, float hi) {
    __nv_bfloat162 v = __float22bfloat162_rn(make_float2(lo, hi));
    return *(uint32_t*)&v;
}
#define LDMX4(d0, d1, d2, d3, addr) \
    asm volatile("ldmatrix.sync.aligned.m8n8.x4.shared.b16 {%0,%1,%2,%3}, [%4];" \
                 : "=r"(d0), "=r"(d1), "=r"(d2), "=r"(d3) : "r"(addr))

// ---------------------------------------------------------------------------
// fp32 -> bf16 streaming convert (8 elems/thread)
// ---------------------------------------------------------------------------
__global__ void cvt_kernel(const float* __restrict__ s, __nv_bfloat16* __restrict__ d) {
    size_t i = (size_t)blockIdx.x * 256 + threadIdx.x;
    const float4* s4 = (const float4*)s;
    float4 v0 = s4[2 * i], v1 = s4[2 * i + 1];
    uint4 o;
    o.x = pack_bf2(v0.x, v0.y);
    o.y = pack_bf2(v0.z, v0.w);
    o.z = pack_bf2(v1.x, v1.y);
    o.w = pack_bf2(v1.z, v1.w);
    ((uint4*)d)[i] = o;
}

// ---------------------------------------------------------------------------
// init: zero r accumulator, preload biases into p/x accumulators
// ---------------------------------------------------------------------------
__global__ void init_kernel(const float* __restrict__ b_p,
                            const float* __restrict__ b_x) {
    int i = blockIdx.x * 256 + threadIdx.x;   // 65536 threads
    g_r[i] = 0.f;
    g_p[i] = b_p[i & (Hh - 1)];
    g_x[i] = b_x[i & (Hh - 1)];
}

// ---------------------------------------------------------------------------
// Big GEMM (M=32768,N=1024,K=1024) on mma.sync m16n8k16 bf16, fused
// tanh*w_w score-reduction epilogue. CTA tile 128x128, 4 warps (64x64),
// 3-stage cp.async pipeline, 2 CTAs/SM, ldmatrix.x4 fragment loads
// (8 instr/kstep instead of 48 LDS.32), XOR-swizzled conflict-free smem.
// ---------------------------------------------------------------------------
__global__ __launch_bounds__(128, 2)
void gemm_scores_tc(const float* __restrict__ bh,
                    const float* __restrict__ ww) {
    extern __shared__ uint32_t sm[];
    float* s_red = (float*)(sm + NSTG * STG_U32);

    int tid = threadIdx.x;
    int w = tid >> 5, lane = tid & 31;
    int gid = lane >> 2, tig = lane & 3;
    int wm = (w >> 1) * 64;         // 0 / 64
    int wn = (w & 1) * 64;          // 0 / 64
    int m0 = blockIdx.y * MT;
    int n0 = blockIdx.x * NT;

    s_red[tid] = 0.f;

    uint32_t sbase = smem_u32(sm);
    const char* Ab = (const char*)(g_hbf + (size_t)m0 * Hh);
    const char* Wb = (const char*)(g_wbf + (size_t)n0 * Hh);

    // full stage fill: 16 x cp.async(16B) per thread (A 8 + B 8)
    auto issue = [&](int s, int kidx) {
        uint32_t aS = sbase + s * (STG_U32 * 4);
        uint32_t bS = aS + A_U32 * 4;
        int kb = kidx * (KC * 2);
#pragma unroll
        for (int u = 0; u < 8; u++) {            // A: 1024 chunks of 16B
            int c = tid + u * 128;
            int row = c >> 3, ch = c & 7;
            const char* g = Ab + (size_t)row * (Hh * 2) + kb + ch * 16;
            uint32_t d = aS + row * 128 + ((ch ^ (row & 7)) * 16);
            asm volatile("cp.async.cg.shared.global [%0], [%1], 16;" :: "r"(d), "l"(g));
        }
#pragma unroll
        for (int u = 0; u < 8; u++) {            // B: 1024 chunks
            int c = tid + u * 128;
            int row = c >> 3, ch = c & 7;
            const char* g = Wb + (size_t)row * (Hh * 2) + kb + ch * 16;
            uint32_t d = bS + row * 128 + ((ch ^ (row & 7)) * 16);
            asm volatile("cp.async.cg.shared.global [%0], [%1], 16;" :: "r"(d), "l"(g));
        }
        asm volatile("cp.async.commit_group;" ::: "memory");
    };

    issue(0, 0); issue(1, 1);

    float acc[4][8][4];
#pragma unroll
    for (int i = 0; i < 4; i++)
#pragma unroll
        for (int j = 0; j < 8; j++)
#pragma unroll
            for (int r = 0; r < 4; r++) acc[i][j][r] = 0.f;

    // ldmatrix per-lane row bases (bytes from smem base, stage 0)
    int l7 = lane & 7;
    int a_row = l7 + ((lane >> 3) & 1) * 8;   // +8 for matrices 1,3
    int a_kg  = (lane >> 4) & 1;              // k-group parity for matrices 2,3
    int b_row = l7 + ((lane >> 4) & 1) * 8;   // +8 for matrices 2,3
    int b_kg  = (lane >> 3) & 1;              // k-group parity for matrices 1,3
    uint32_t aRow[4], bRow[4];
#pragma unroll
    for (int i = 0; i < 4; i++) aRow[i] = sbase + (wm + i * 16 + a_row) * 128;
#pragma unroll
    for (int jp = 0; jp < 4; jp++)
        bRow[jp] = sbase + A_U32 * 4 + (wn + jp * 16 + b_row) * 128;

    for (int ks = 0; ks < KCHUNKS; ks++) {
        if (ks < KCHUNKS - 1)
            asm volatile("cp.async.wait_group 1;" ::: "memory");
        else
            asm volatile("cp.async.wait_group 0;" ::: "memory");
        __syncthreads();
        if (ks + 2 < KCHUNKS) issue((ks + 2) % NSTG, ks + 2);

        uint32_t so = (ks % NSTG) * (STG_U32 * 4);
#pragma unroll
        for (int kk = 0; kk < 4; kk++) {
            uint32_t kxa = (uint32_t)(((2 * kk + a_kg) ^ l7) << 4) + so;
            uint32_t kxb = (uint32_t)(((2 * kk + b_kg) ^ l7) << 4) + so;
            uint32_t af[4][4];
#pragma unroll
            for (int i = 0; i < 4; i++)
                LDMX4(af[i][0], af[i][1], af[i][2], af[i][3], aRow[i] + kxa);
            uint32_t bfr[8][2];
#pragma unroll
            for (int jp = 0; jp < 4; jp++)
                LDMX4(bfr[2 * jp][0], bfr[2 * jp][1],
                      bfr[2 * jp + 1][0], bfr[2 * jp + 1][1], bRow[jp] + kxb);
#pragma unroll
            for (int i = 0; i < 4; i++)
#pragma unroll
                for (int j = 0; j < 8; j++)
                    asm volatile(
                        "mma.sync.aligned.m16n8k16.row.col.f32.bf16.bf16.f32 "
                        "{%0,%1,%2,%3}, {%4,%5,%6,%7}, {%8,%9}, {%0,%1,%2,%3};"
                        : "+f"(acc[i][j][0]), "+f"(acc[i][j][1]),
                          "+f"(acc[i][j][2]), "+f"(acc[i][j][3])
                        : "r"(af[i][0]), "r"(af[i][1]), "r"(af[i][2]), "r"(af[i][3]),
                          "r"(bfr[j][0]), "r"(bfr[j][1]));
        }
    }

    // Fused epilogue: part[m] = sum_n tanh(acc + bh[n]) * ww[n]
    float bhv[8][2], wwv[8][2];
#pragma unroll
    for (int j = 0; j < 8; j++) {
#pragma unroll
        for (int h = 0; h < 2; h++) {
            int n = n0 + wn + j * 8 + 2 * tig + h;
            bhv[j][h] = bh[n];
            wwv[j][h] = ww[n];
        }
    }
#pragma unroll
    for (int i = 0; i < 4; i++) {
        float p0 = 0.f, p1 = 0.f;
#pragma unroll
        for (int j = 0; j < 8; j++) {
            p0 += tanh_fast(acc[i][j][0] + bhv[j][0]) * wwv[j][0];
            p0 += tanh_fast(acc[i][j][1] + bhv[j][1]) * wwv[j][1];
            p1 += tanh_fast(acc[i][j][2] + bhv[j][0]) * wwv[j][0];
            p1 += tanh_fast(acc[i][j][3] + bhv[j][1]) * wwv[j][1];
        }
        p0 += __shfl_xor_sync(0xffffffffu, p0, 1);
        p0 += __shfl_xor_sync(0xffffffffu, p0, 2);
        p1 += __shfl_xor_sync(0xffffffffu, p1, 1);
        p1 += __shfl_xor_sync(0xffffffffu, p1, 2);
        if (tig == 0) {
            atomicAdd(&s_red[wm + i * 16 + gid], p0);
            atomicAdd(&s_red[wm + i * 16 + gid + 8], p1);
        }
    }
    __syncthreads();
    g_spart[blockIdx.x * Mtot + m0 + tid] = s_red[tid];
}

// ---------------------------------------------------------------------------
// softmax over T per batch row (sums the GX partial-score slabs)
// ---------------------------------------------------------------------------
__global__ void softmax_kernel() {
    __shared__ float red[Tt];
    int b = blockIdx.x;
    int t = threadIdx.x;
    float s = 0.f;
#pragma unroll
    for (int p = 0; p < GX; p++) s += g_spart[p * Mtot + b * Tt + t];
    red[t] = s;
    __syncthreads();
    for (int off = 256; off > 0; off >>= 1) {
        if (t < off) red[t] = fmaxf(red[t], red[t + off]);
        __syncthreads();
    }
    float mx = red[0];
    __syncthreads();
    float e = expf(s - mx);
    red[t] = e;
    __syncthreads();
    for (int off = 256; off > 0; off >>= 1) {
        if (t < off) red[t] += red[t + off];
        __syncthreads();
    }
    g_alpha[b * Tt + t] = e / red[0];
}

// ---------------------------------------------------------------------------
// r[b,h] += sum_t alpha[b,t]*hidden[b,t,h] — reads bf16 copy (half traffic),
// each thread covers an h-pair; T split 4 ways for MLP.
// ---------------------------------------------------------------------------
__global__ void wsum_kernel() {
    __shared__ float a_s[128];
    int seg = blockIdx.z;
    int b = blockIdx.y;
    int h2 = blockIdx.x * 256 + threadIdx.x;       // bf16x2 index, 0..511
    if (threadIdx.x < 128) a_s[threadIdx.x] = g_alpha[b * Tt + seg * 128 + threadIdx.x];
    __syncthreads();
    const __nv_bfloat162* hp = (const __nv_bfloat162*)g_hbf
        + ((size_t)b * Tt + seg * 128) * (Hh / 2) + h2;
    float ax[4], ay[4];
#pragma unroll
    for (int u = 0; u < 4; u++) { ax[u] = 0.f; ay[u] = 0.f; }
    for (int t = 0; t < 128; t += 4) {
#pragma unroll
        for (int u = 0; u < 4; u++) {
            float2 v = __bfloat1622float2(hp[(size_t)(t + u) * (Hh / 2)]);
            float a = a_s[t + u];
            ax[u] = fmaf(a, v.x, ax[u]);
            ay[u] = fmaf(a, v.y, ay[u]);
        }
    }
    atomicAdd(&g_r[b * Hh + 2 * h2],     (ax[0] + ax[1]) + (ax[2] + ax[3]));
    atomicAdd(&g_r[b * Hh + 2 * h2 + 1], (ay[0] + ay[1]) + (ay[2] + ay[3]));
}

// ---------------------------------------------------------------------------
// small GEMM: out[b,n] += V[b,:] . W[n,:]   (out pre-initialized with bias)
// blockIdx.z selects the p-path (r@W_p) or x-path (hidden_last@W_x).
// ---------------------------------------------------------------------------
__global__ __launch_bounds__(256)
void small_gemm_kernel(const float* __restrict__ hidden,
                       const float* __restrict__ W_p,
                       const float* __restrict__ W_x) {
    __shared__ float Vs[32][68];
    __shared__ float Ws[32][68];

    int sel = blockIdx.z;
    const float* W = sel ? W_x : W_p;
    const float* V;
    size_t vstride;
    if (sel) { V = hidden + (size_t)(Tt - 1) * Hh; vstride = (size_t)Tt * Hh; }
    else     { V = g_r; vstride = Hh; }

    int tid = threadIdx.x;
    int nBase = blockIdx.x * 64;
    int kBase = blockIdx.y * 128;

    int tn = tid & 15;
    int tb = tid >> 4;
    int lrow = tid >> 3;
    int lcol = (tid & 7) << 2;

    float acc[4][4];
#pragma unroll
    for (int i = 0; i < 4; i++)
#pragma unroll
        for (int j = 0; j < 4; j++) acc[i][j] = 0.f;

    for (int kc = 0; kc < 128; kc += 32) {
        int kg = kBase + kc;
        float4 v0 = *(const float4*)(V + (size_t)lrow * vstride + kg + lcol);
        float4 v1 = *(const float4*)(V + (size_t)(lrow + 32) * vstride + kg + lcol);
        float4 w0 = *(const float4*)(W + (size_t)(nBase + lrow) * Hh + kg + lcol);
        float4 w1 = *(const float4*)(W + (size_t)(nBase + lrow + 32) * Hh + kg + lcol);
        __syncthreads();
        Vs[lcol + 0][lrow] = v0.x; Vs[lcol + 1][lrow] = v0.y;
        Vs[lcol + 2][lrow] = v0.z; Vs[lcol + 3][lrow] = v0.w;
        Vs[lcol + 0][lrow + 32] = v1.x; Vs[lcol + 1][lrow + 32] = v1.y;
        Vs[lcol + 2][lrow + 32] = v1.z; Vs[lcol + 3][lrow + 32] = v1.w;
        Ws[lcol + 0][lrow] = w0.x; Ws[lcol + 1][lrow] = w0.y;
        Ws[lcol + 2][lrow] = w0.z; Ws[lcol + 3][lrow] = w0.w;
        Ws[lcol + 0][lrow + 32] = w1.x; Ws[lcol + 1][lrow + 32] = w1.y;
        Ws[lcol + 2][lrow + 32] = w1.z; Ws[lcol + 3][lrow + 32] = w1.w;
        __syncthreads();
#pragma unroll
        for (int k = 0; k < 32; k++) {
            float vb[4], wnv[4];
#pragma unroll
            for (int i = 0; i < 4; i++) vb[i] = Vs[k][tb * 4 + i];
#pragma unroll
            for (int j = 0; j < 4; j++) wnv[j] = Ws[k][tn * 4 + j];
#pragma unroll
            for (int i = 0; i < 4; i++)
#pragma unroll
                for (int j = 0; j < 4; j++)
                    acc[i][j] = fmaf(vb[i], wnv[j], acc[i][j]);
        }
    }

    float* out = sel ? g_x : g_p;
#pragma unroll
    for (int i = 0; i < 4; i++)
#pragma unroll
        for (int j = 0; j < 4; j++)
            atomicAdd(&out[(tb * 4 + i) * Hh + nBase + tn * 4 + j], acc[i][j]);
}

// ---------------------------------------------------------------------------
// output[b1,b2,h] = tanh(p[b1,h] + x[b2,h])
// ---------------------------------------------------------------------------
__global__ void output_kernel(float* __restrict__ out) {
    int h = blockIdx.x * 256 + threadIdx.x;
    int b2 = blockIdx.y;
    int b1 = blockIdx.z;
    out[((size_t)b1 * Bb + b2) * Hh + h] =
        tanhf(g_p[b1 * Hh + h] + g_x[b2 * Hh + h]);
}

// ---------------------------------------------------------------------------
// launch
// ---------------------------------------------------------------------------
extern "C" void kernel_launch(void* const* d_in, const int* in_sizes, int n_in,
                              void* d_out, int out_size) {
    (void)in_sizes; (void)n_in; (void)out_size;
    const float* hidden = (const float*)d_in[0];
    // d_in[1] aspect, d_in[4] W_v, d_in[5] b_v, d_in[7] w_b are provably dead
    // (softmax shift-invariance kills the per-batch-constant aspect branch).
    const float* W_h = (const float*)d_in[2];
    const float* b_h = (const float*)d_in[3];
    const float* w_w = (const float*)d_in[6];
    const float* W_p = (const float*)d_in[8];
    const float* b_p = (const float*)d_in[9];
    const float* W_x = (const float*)d_in[10];
    const float* b_x = (const float*)d_in[11];
    float* out = (float*)d_out;

    cudaFuncSetAttribute(gemm_scores_tc,
                         cudaFuncAttributeMaxDynamicSharedMemorySize, SMEM_BYTES);

    __nv_bfloat16* hbf = nullptr;
    __nv_bfloat16* wbf = nullptr;
    cudaGetSymbolAddress((void**)&hbf, g_hbf);
    cudaGetSymbolAddress((void**)&wbf, g_wbf);

    cvt_kernel<<<(Mtot * (Hh / 8)) / 256, 256>>>(hidden, hbf);   // 16384 blocks
    cvt_kernel<<<(Hh * (Hh / 8)) / 256, 256>>>(W_h, wbf);        // 512 blocks
    init_kernel<<<256, 256>>>(b_p, b_x);
    gemm_scores_tc<<<dim3(GX, Mtot / MT), 128, SMEM_BYTES>>>(b_h, w_w);
    softmax_kernel<<<Bb, Tt>>>();
    wsum_kernel<<<dim3(Hh / 512, Bb, 4), 256>>>();
    small_gemm_kernel<<<dim3(Hh / 64, Hh / 128, 2), 256>>>(hidden, W_p, W_x);
    output_kernel<<<dim3(Hh / 256, Bb, Bb), 256>>>(out);
}

// round 10
// speedup vs baseline: 10.8533x; 1.0274x over previous
#include <cuda_runtime.h>
#include <cuda_bf16.h>
#include <math.h>
#include <stdint.h>

// ---------------------------------------------------------------------------
// Problem constants
// ---------------------------------------------------------------------------
#define Bb 64
#define Tt 512
#define Hh 1024
#define Mtot (Bb * Tt)   // 32768

// Big-GEMM tiling: CTA 128x128, 4 warps (64x64 each), 2 CTAs/SM
#define MT 128
#define NT 128
#define KC 64                        // K per smem stage (64 bf16 = 128B rows)
#define NSTG 3
#define KCHUNKS (Hh / KC)            // 16
#define GX (Hh / NT)                 // 8
#define A_U32 (MT * KC / 2)          // 4096 uint32 (bf16 pairs)
#define STG_U32 ((MT + NT) * KC / 2) // 8192 uint32 = 32KB/stage
#define SMEM_U32 (NSTG * STG_U32 + 128)
#define SMEM_BYTES (SMEM_U32 * 4)    // 98816

// ---------------------------------------------------------------------------
// Scratch (device globals: no allocation allowed)
// ---------------------------------------------------------------------------
__device__ __align__(256) __nv_bfloat16 g_hbf[(size_t)Mtot * Hh];  // 64MB
__device__ __align__(256) __nv_bfloat16 g_wbf[(size_t)Hh * Hh];    // 2MB
__device__ float g_spart[GX * Mtot];   // per-N-tile partial scores (1MB)
__device__ float g_alpha[Mtot];
__device__ float g_r[Bb * Hh];
__device__ float g_p[Bb * Hh];
__device__ float g_x[Bb * Hh];

// ---------------------------------------------------------------------------
// helpers
// ---------------------------------------------------------------------------
__device__ __forceinline__ uint32_t smem_u32(const void* p) {
    uint32_t a;
    asm("{ .reg .u64 t; cvta.to.shared.u64 t, %1; cvt.u32.u64 %0, t; }" : "=r"(a) : "l"(p));
    return a;
}
__device__ __forceinline__ float tanh_fast(float x) {
    float y;
    asm("tanh.approx.f32 %0, %1;" : "=f"(y) : "f"(x));
    return y;
}
__device__ __forceinline__ uint32_t pack_bf2(float lo, float hi) {
    __nv_bfloat162 v = __float22bfloat162_rn(make_float2(lo, hi));
    return *(uint32_t*)&v;
}
#define LDMX4(d0, d1, d2, d3, addr) \
    asm volatile("ldmatrix.sync.aligned.m8n8.x4.shared.b16 {%0,%1,%2,%3}, [%4];" \
                 : "=r"(d0), "=r"(d1), "=r"(d2), "=r"(d3) : "r"(addr))

// ---------------------------------------------------------------------------
// fp32 -> bf16 streaming convert (8 elems/thread)
// ---------------------------------------------------------------------------
__global__ void cvt_kernel(const float* __restrict__ s, __nv_bfloat16* __restrict__ d) {
    size_t i = (size_t)blockIdx.x * 256 + threadIdx.x;
    const float4* s4 = (const float4*)s;
    float4 v0 = s4[2 * i], v1 = s4[2 * i + 1];
    uint4 o;
    o.x = pack_bf2(v0.x, v0.y);
    o.y = pack_bf2(v0.z, v0.w);
    o.z = pack_bf2(v1.x, v1.y);
    o.w = pack_bf2(v1.z, v1.w);
    ((uint4*)d)[i] = o;
}

// ---------------------------------------------------------------------------
// init: zero r accumulator, preload biases into p/x accumulators
// ---------------------------------------------------------------------------
__global__ void init_kernel(const float* __restrict__ b_p,
                            const float* __restrict__ b_x) {
    int i = blockIdx.x * 256 + threadIdx.x;   // 65536 threads
    g_r[i] = 0.f;
    g_p[i] = b_p[i & (Hh - 1)];
    g_x[i] = b_x[i & (Hh - 1)];
}

// ---------------------------------------------------------------------------
// Big GEMM (M=32768,N=1024,K=1024) on mma.sync m16n8k16 bf16, fused
// tanh*w_w score-reduction epilogue. CTA tile 128x128, 4 warps (64x64),
// 3-stage cp.async pipeline, 2 CTAs/SM, ldmatrix.x4 fragment loads.
// kstep0 fragments of chunk ks+1 are prefetched BEFORE the barrier
// (stage ks+1 is complete+visible after this iteration's wait_group 0 +
// barrier), so post-barrier MMAs issue with zero LDSM latency.
// ---------------------------------------------------------------------------
__global__ __launch_bounds__(128, 2)
void gemm_scores_tc(const float* __restrict__ bh,
                    const float* __restrict__ ww) {
    extern __shared__ uint32_t sm[];
    float* s_red = (float*)(sm + NSTG * STG_U32);

    int tid = threadIdx.x;
    int w = tid >> 5, lane = tid & 31;
    int gid = lane >> 2, tig = lane & 3;
    int wm = (w >> 1) * 64;         // 0 / 64
    int wn = (w & 1) * 64;          // 0 / 64
    int m0 = blockIdx.y * MT;
    int n0 = blockIdx.x * NT;

    s_red[tid] = 0.f;

    uint32_t sbase = smem_u32(sm);
    const char* Ab = (const char*)(g_hbf + (size_t)m0 * Hh);
    const char* Wb = (const char*)(g_wbf + (size_t)n0 * Hh);

    // full stage fill: 16 x cp.async(16B) per thread (A 8 + B 8)
    auto issue = [&](int s, int kidx) {
        uint32_t aS = sbase + s * (STG_U32 * 4);
        uint32_t bS = aS + A_U32 * 4;
        int kb = kidx * (KC * 2);
#pragma unroll
        for (int u = 0; u < 8; u++) {            // A: 1024 chunks of 16B
            int c = tid + u * 128;
            int row = c >> 3, ch = c & 7;
            const char* g = Ab + (size_t)row * (Hh * 2) + kb + ch * 16;
            uint32_t d = aS + row * 128 + ((ch ^ (row & 7)) * 16);
            asm volatile("cp.async.cg.shared.global [%0], [%1], 16;" :: "r"(d), "l"(g));
        }
#pragma unroll
        for (int u = 0; u < 8; u++) {            // B: 1024 chunks
            int c = tid + u * 128;
            int row = c >> 3, ch = c & 7;
            const char* g = Wb + (size_t)row * (Hh * 2) + kb + ch * 16;
            uint32_t d = bS + row * 128 + ((ch ^ (row & 7)) * 16);
            asm volatile("cp.async.cg.shared.global [%0], [%1], 16;" :: "r"(d), "l"(g));
        }
        asm volatile("cp.async.commit_group;" ::: "memory");
    };

    issue(0, 0); issue(1, 1);

    float acc[4][8][4];
#pragma unroll
    for (int i = 0; i < 4; i++)
#pragma unroll
        for (int j = 0; j < 8; j++)
#pragma unroll
            for (int r = 0; r < 4; r++) acc[i][j][r] = 0.f;

    // ldmatrix per-lane row bases (bytes from smem base, stage 0)
    int l7 = lane & 7;
    int a_row = l7 + ((lane >> 3) & 1) * 8;   // +8 for matrices 1,3
    int a_kg  = (lane >> 4) & 1;              // k-group parity for matrices 2,3
    int b_row = l7 + ((lane >> 4) & 1) * 8;   // +8 for matrices 2,3
    int b_kg  = (lane >> 3) & 1;              // k-group parity for matrices 1,3
    uint32_t aRow[4], bRow[4];
#pragma unroll
    for (int i = 0; i < 4; i++) aRow[i] = sbase + (wm + i * 16 + a_row) * 128;
#pragma unroll
    for (int jp = 0; jp < 4; jp++)
        bRow[jp] = sbase + A_U32 * 4 + (wn + jp * 16 + b_row) * 128;

    // fragment loads for kstep kk at stage byte-offset so
    auto load_a = [&](uint32_t (&af)[4][4], uint32_t so, int kk) {
        uint32_t kxa = (uint32_t)(((2 * kk + a_kg) ^ l7) << 4) + so;
#pragma unroll
        for (int i = 0; i < 4; i++)
            LDMX4(af[i][0], af[i][1], af[i][2], af[i][3], aRow[i] + kxa);
    };
    auto load_b = [&](uint32_t (&bfr)[8][2], uint32_t so, int kk) {
        uint32_t kxb = (uint32_t)(((2 * kk + b_kg) ^ l7) << 4) + so;
#pragma unroll
        for (int jp = 0; jp < 4; jp++)
            LDMX4(bfr[2 * jp][0], bfr[2 * jp][1],
                  bfr[2 * jp + 1][0], bfr[2 * jp + 1][1], bRow[jp] + kxb);
    };
    auto mma_all = [&](uint32_t (&af)[4][4], uint32_t (&bfr)[8][2]) {
#pragma unroll
        for (int i = 0; i < 4; i++)
#pragma unroll
            for (int j = 0; j < 8; j++)
                asm volatile(
                    "mma.sync.aligned.m16n8k16.row.col.f32.bf16.bf16.f32 "
                    "{%0,%1,%2,%3}, {%4,%5,%6,%7}, {%8,%9}, {%0,%1,%2,%3};"
                    : "+f"(acc[i][j][0]), "+f"(acc[i][j][1]),
                      "+f"(acc[i][j][2]), "+f"(acc[i][j][3])
                    : "r"(af[i][0]), "r"(af[i][1]), "r"(af[i][2]), "r"(af[i][3]),
                      "r"(bfr[j][0]), "r"(bfr[j][1]));
    };

    uint32_t afp[4][4], bfp[8][2];      // prefetched kstep0 fragments

    for (int ks = 0; ks < KCHUNKS; ks++) {
        asm volatile("cp.async.wait_group 0;" ::: "memory");
        __syncthreads();
        if (ks + 2 < KCHUNKS) issue((ks + 2) % NSTG, ks + 2);

        uint32_t so = (ks % NSTG) * (STG_U32 * 4);
        if (ks == 0) { load_a(afp, so, 0); load_b(bfp, so, 0); }  // startup only

        mma_all(afp, bfp);              // kstep 0: fragments already resident
#pragma unroll
        for (int kk = 1; kk < 4; kk++) {
            uint32_t af[4][4], bfr[8][2];
            load_a(af, so, kk);
            load_b(bfr, so, kk);
            mma_all(af, bfr);
        }
        if (ks + 1 < KCHUNKS) {         // prefetch next chunk's kstep0 frags
            uint32_t son = ((ks + 1) % NSTG) * (STG_U32 * 4);
            load_a(afp, son, 0);
            load_b(bfp, son, 0);
        }
    }

    // Fused epilogue: part[m] = sum_n tanh(acc + bh[n]) * ww[n]
    float bhv[8][2], wwv[8][2];
#pragma unroll
    for (int j = 0; j < 8; j++) {
#pragma unroll
        for (int h = 0; h < 2; h++) {
            int n = n0 + wn + j * 8 + 2 * tig + h;
            bhv[j][h] = bh[n];
            wwv[j][h] = ww[n];
        }
    }
#pragma unroll
    for (int i = 0; i < 4; i++) {
        float p0 = 0.f, p1 = 0.f;
#pragma unroll
        for (int j = 0; j < 8; j++) {
            p0 += tanh_fast(acc[i][j][0] + bhv[j][0]) * wwv[j][0];
            p0 += tanh_fast(acc[i][j][1] + bhv[j][1]) * wwv[j][1];
            p1 += tanh_fast(acc[i][j][2] + bhv[j][0]) * wwv[j][0];
            p1 += tanh_fast(acc[i][j][3] + bhv[j][1]) * wwv[j][1];
        }
        p0 += __shfl_xor_sync(0xffffffffu, p0, 1);
        p0 += __shfl_xor_sync(0xffffffffu, p0, 2);
        p1 += __shfl_xor_sync(0xffffffffu, p1, 1);
        p1 += __shfl_xor_sync(0xffffffffu, p1, 2);
        if (tig == 0) {
            atomicAdd(&s_red[wm + i * 16 + gid], p0);
            atomicAdd(&s_red[wm + i * 16 + gid + 8], p1);
        }
    }
    __syncthreads();
    g_spart[blockIdx.x * Mtot + m0 + tid] = s_red[tid];
}

// ---------------------------------------------------------------------------
// softmax over T per batch row (sums the GX partial-score slabs)
// ---------------------------------------------------------------------------
__global__ void softmax_kernel() {
    __shared__ float red[Tt];
    int b = blockIdx.x;
    int t = threadIdx.x;
    float s = 0.f;
#pragma unroll
    for (int p = 0; p < GX; p++) s += g_spart[p * Mtot + b * Tt + t];
    red[t] = s;
    __syncthreads();
    for (int off = 256; off > 0; off >>= 1) {
        if (t < off) red[t] = fmaxf(red[t], red[t + off]);
        __syncthreads();
    }
    float mx = red[0];
    __syncthreads();
    float e = expf(s - mx);
    red[t] = e;
    __syncthreads();
    for (int off = 256; off > 0; off >>= 1) {
        if (t < off) red[t] += red[t + off];
        __syncthreads();
    }
    g_alpha[b * Tt + t] = e / red[0];
}

// ---------------------------------------------------------------------------
// r[b,h] += sum_t alpha[b,t]*hidden[b,t,h] — reads bf16 copy (half traffic),
// each thread covers an h-pair; T split 4 ways for MLP.
// ---------------------------------------------------------------------------
__global__ void wsum_kernel() {
    __shared__ float a_s[128];
    int seg = blockIdx.z;
    int b = blockIdx.y;
    int h2 = blockIdx.x * 256 + threadIdx.x;       // bf16x2 index, 0..511
    if (threadIdx.x < 128) a_s[threadIdx.x] = g_alpha[b * Tt + seg * 128 + threadIdx.x];
    __syncthreads();
    const __nv_bfloat162* hp = (const __nv_bfloat162*)g_hbf
        + ((size_t)b * Tt + seg * 128) * (Hh / 2) + h2;
    float ax[4], ay[4];
#pragma unroll
    for (int u = 0; u < 4; u++) { ax[u] = 0.f; ay[u] = 0.f; }
    for (int t = 0; t < 128; t += 4) {
#pragma unroll
        for (int u = 0; u < 4; u++) {
            float2 v = __bfloat1622float2(hp[(size_t)(t + u) * (Hh / 2)]);
            float a = a_s[t + u];
            ax[u] = fmaf(a, v.x, ax[u]);
            ay[u] = fmaf(a, v.y, ay[u]);
        }
    }
    atomicAdd(&g_r[b * Hh + 2 * h2],     (ax[0] + ax[1]) + (ax[2] + ax[3]));
    atomicAdd(&g_r[b * Hh + 2 * h2 + 1], (ay[0] + ay[1]) + (ay[2] + ay[3]));
}

// ---------------------------------------------------------------------------
// small GEMM: out[b,n] += V[b,:] . W[n,:]   (out pre-initialized with bias)
// blockIdx.z selects the p-path (r@W_p) or x-path (hidden_last@W_x).
// ---------------------------------------------------------------------------
__global__ __launch_bounds__(256)
void small_gemm_kernel(const float* __restrict__ hidden,
                       const float* __restrict__ W_p,
                       const float* __restrict__ W_x) {
    __shared__ float Vs[32][68];
    __shared__ float Ws[32][68];

    int sel = blockIdx.z;
    const float* W = sel ? W_x : W_p;
    const float* V;
    size_t vstride;
    if (sel) { V = hidden + (size_t)(Tt - 1) * Hh; vstride = (size_t)Tt * Hh; }
    else     { V = g_r; vstride = Hh; }

    int tid = threadIdx.x;
    int nBase = blockIdx.x * 64;
    int kBase = blockIdx.y * 128;

    int tn = tid & 15;
    int tb = tid >> 4;
    int lrow = tid >> 3;
    int lcol = (tid & 7) << 2;

    float acc[4][4];
#pragma unroll
    for (int i = 0; i < 4; i++)
#pragma unroll
        for (int j = 0; j < 4; j++) acc[i][j] = 0.f;

    for (int kc = 0; kc < 128; kc += 32) {
        int kg = kBase + kc;
        float4 v0 = *(const float4*)(V + (size_t)lrow * vstride + kg + lcol);
        float4 v1 = *(const float4*)(V + (size_t)(lrow + 32) * vstride + kg + lcol);
        float4 w0 = *(const float4*)(W + (size_t)(nBase + lrow) * Hh + kg + lcol);
        float4 w1 = *(const float4*)(W + (size_t)(nBase + lrow + 32) * Hh + kg + lcol);
        __syncthreads();
        Vs[lcol + 0][lrow] = v0.x; Vs[lcol + 1][lrow] = v0.y;
        Vs[lcol + 2][lrow] = v0.z; Vs[lcol + 3][lrow] = v0.w;
        Vs[lcol + 0][lrow + 32] = v1.x; Vs[lcol + 1][lrow + 32] = v1.y;
        Vs[lcol + 2][lrow + 32] = v1.z; Vs[lcol + 3][lrow + 32] = v1.w;
        Ws[lcol + 0][lrow] = w0.x; Ws[lcol + 1][lrow] = w0.y;
        Ws[lcol + 2][lrow] = w0.z; Ws[lcol + 3][lrow] = w0.w;
        Ws[lcol + 0][lrow + 32] = w1.x; Ws[lcol + 1][lrow + 32] = w1.y;
        Ws[lcol + 2][lrow + 32] = w1.z; Ws[lcol + 3][lrow + 32] = w1.w;
        __syncthreads();
#pragma unroll
        for (int k = 0; k < 32; k++) {
            float vb[4], wnv[4];
#pragma unroll
            for (int i = 0; i < 4; i++) vb[i] = Vs[k][tb * 4 + i];
#pragma unroll
            for (int j = 0; j < 4; j++) wnv[j] = Ws[k][tn * 4 + j];
#pragma unroll
            for (int i = 0; i < 4; i++)
#pragma unroll
                for (int j = 0; j < 4; j++)
                    acc[i][j] = fmaf(vb[i], wnv[j], acc[i][j]);
        }
    }

    float* out = sel ? g_x : g_p;
#pragma unroll
    for (int i = 0; i < 4; i++)
#pragma unroll
        for (int j = 0; j < 4; j++)
            atomicAdd(&out[(tb * 4 + i) * Hh + nBase + tn * 4 + j], acc[i][j]);
}

// ---------------------------------------------------------------------------
// output[b1,b2,h] = tanh(p[b1,h] + x[b2,h])
// ---------------------------------------------------------------------------
__global__ void output_kernel(float* __restrict__ out) {
    int h = blockIdx.x * 256 + threadIdx.x;
    int b2 = blockIdx.y;
    int b1 = blockIdx.z;
    out[((size_t)b1 * Bb + b2) * Hh + h] =
        tanhf(g_p[b1 * Hh + h] + g_x[b2 * Hh + h]);
}

// ---------------------------------------------------------------------------
// launch
// ---------------------------------------------------------------------------
extern "C" void kernel_launch(void* const* d_in, const int* in_sizes, int n_in,
                              void* d_out, int out_size) {
    (void)in_sizes; (void)n_in; (void)out_size;
    const float* hidden = (const float*)d_in[0];
    // d_in[1] aspect, d_in[4] W_v, d_in[5] b_v, d_in[7] w_b are provably dead
    // (softmax shift-invariance kills the per-batch-constant aspect branch).
    const float* W_h = (const float*)d_in[2];
    const float* b_h = (const float*)d_in[3];
    const float* w_w = (const float*)d_in[6];
    const float* W_p = (const float*)d_in[8];
    const float* b_p = (const float*)d_in[9];
    const float* W_x = (const float*)d_in[10];
    const float* b_x = (const float*)d_in[11];
    float* out = (float*)d_out;

    cudaFuncSetAttribute(gemm_scores_tc,
                         cudaFuncAttributeMaxDynamicSharedMemorySize, SMEM_BYTES);

    __nv_bfloat16* hbf = nullptr;
    __nv_bfloat16* wbf = nullptr;
    cudaGetSymbolAddress((void**)&hbf, g_hbf);
    cudaGetSymbolAddress((void**)&wbf, g_wbf);

    cvt_kernel<<<(Mtot * (Hh / 8)) / 256, 256>>>(hidden, hbf);   // 16384 blocks
    cvt_kernel<<<(Hh * (Hh / 8)) / 256, 256>>>(W_h, wbf);        // 512 blocks
    init_kernel<<<256, 256>>>(b_p, b_x);
    gemm_scores_tc<<<dim3(GX, Mtot / MT), 128, SMEM_BYTES>>>(b_h, w_w);
    softmax_kernel<<<Bb, Tt>>>();
    wsum_kernel<<<dim3(Hh / 512, Bb, 4), 256>>>();
    small_gemm_kernel<<<dim3(Hh / 64, Hh / 128, 2), 256>>>(hidden, W_p, W_x);
    output_kernel<<<dim3(Hh / 256, Bb, Bb), 256>>>(out);
}

// round 11
// speedup vs baseline: 10.9096x; 1.0052x over previous
#include <cuda_runtime.h>
#include <cuda_bf16.h>
#include <math.h>
#include <stdint.h>

// ---------------------------------------------------------------------------
// Problem constants
// ---------------------------------------------------------------------------
#define Bb 64
#define Tt 512
#define Hh 1024
#define Mtot (Bb * Tt)   // 32768

// Big-GEMM tiling: CTA 128x128, 4 warps (64x64 each), 2 CTAs/SM
#define MT 128
#define NT 128
#define KC 32                        // K per smem stage (32 bf16 = 64B rows)
#define NSTG 6
#define KCHUNKS (Hh / KC)            // 32
#define GX (Hh / NT)                 // 8
#define A_U32 (MT * KC / 2)          // 2048 uint32
#define STG_U32 ((MT + NT) * KC / 2) // 4096 uint32 = 16KB/stage
#define STG_BYTES (STG_U32 * 4)
#define SMEM_U32 (NSTG * STG_U32 + 128)
#define SMEM_BYTES (SMEM_U32 * 4)    // 98816

// ---------------------------------------------------------------------------
// Scratch (device globals: no allocation allowed)
// ---------------------------------------------------------------------------
__device__ __align__(256) __nv_bfloat16 g_hbf[(size_t)Mtot * Hh];  // 64MB
__device__ __align__(256) __nv_bfloat16 g_wbf[(size_t)Hh * Hh];    // 2MB
__device__ float g_spart[GX * Mtot];   // per-N-tile partial scores (1MB)
__device__ float g_alpha[Mtot];
__device__ float g_r[Bb * Hh];
__device__ float g_p[Bb * Hh];
__device__ float g_x[Bb * Hh];

// ---------------------------------------------------------------------------
// helpers
// ---------------------------------------------------------------------------
__device__ __forceinline__ uint32_t smem_u32(const void* p) {
    uint32_t a;
    asm("{ .reg .u64 t; cvta.to.shared.u64 t, %1; cvt.u32.u64 %0, t; }" : "=r"(a) : "l"(p));
    return a;
}
__device__ __forceinline__ float tanh_fast(float x) {
    float y;
    asm("tanh.approx.f32 %0, %1;" : "=f"(y) : "f"(x));
    return y;
}
__device__ __forceinline__ uint32_t pack_bf2(float lo, float hi) {
    __nv_bfloat162 v = __float22bfloat162_rn(make_float2(lo, hi));
    return *(uint32_t*)&v;
}
#define LDMX4(d0, d1, d2, d3, addr) \
    asm volatile("ldmatrix.sync.aligned.m8n8.x4.shared.b16 {%0,%1,%2,%3}, [%4];" \
                 : "=r"(d0), "=r"(d1), "=r"(d2), "=r"(d3) : "r"(addr))

// ---------------------------------------------------------------------------
// fp32 -> bf16 streaming convert (8 elems/thread)
// ---------------------------------------------------------------------------
__global__ void cvt_kernel(const float* __restrict__ s, __nv_bfloat16* __restrict__ d) {
    size_t i = (size_t)blockIdx.x * 256 + threadIdx.x;
    const float4* s4 = (const float4*)s;
    float4 v0 = s4[2 * i], v1 = s4[2 * i + 1];
    uint4 o;
    o.x = pack_bf2(v0.x, v0.y);
    o.y = pack_bf2(v0.z, v0.w);
    o.z = pack_bf2(v1.x, v1.y);
    o.w = pack_bf2(v1.z, v1.w);
    ((uint4*)d)[i] = o;
}

// ---------------------------------------------------------------------------
// init: zero r accumulator, preload biases into p/x accumulators
// ---------------------------------------------------------------------------
__global__ void init_kernel(const float* __restrict__ b_p,
                            const float* __restrict__ b_x) {
    int i = blockIdx.x * 256 + threadIdx.x;   // 65536 threads
    g_r[i] = 0.f;
    g_p[i] = b_p[i & (Hh - 1)];
    g_x[i] = b_x[i & (Hh - 1)];
}

// ---------------------------------------------------------------------------
// Big GEMM (M=32768,N=1024,K=1024) on mma.sync m16n8k16 bf16, fused
// tanh*w_w score-reduction epilogue. CTA tile 128x128, 4 warps (64x64),
// DEEP 6-stage cp.async pipeline (KC=32, fill issued 4 chunks ahead,
// wait_group 2 => each fill has ~3 chunk-times of slack), 2 CTAs/SM,
// ldmatrix.x4 fragment loads, kstep0 fragments prefetched across the
// barrier, XOR-swizzled conflict-free smem (64B rows, 4x16B chunks).
// ---------------------------------------------------------------------------
__global__ __launch_bounds__(128, 2)
void gemm_scores_tc(const float* __restrict__ bh,
                    const float* __restrict__ ww) {
    extern __shared__ uint32_t sm[];
    float* s_red = (float*)(sm + NSTG * STG_U32);

    int tid = threadIdx.x;
    int w = tid >> 5, lane = tid & 31;
    int gid = lane >> 2, tig = lane & 3;
    int wm = (w >> 1) * 64;         // 0 / 64
    int wn = (w & 1) * 64;          // 0 / 64
    int m0 = blockIdx.y * MT;
    int n0 = blockIdx.x * NT;

    s_red[tid] = 0.f;

    uint32_t sbase = smem_u32(sm);
    const char* Ab = (const char*)(g_hbf + (size_t)m0 * Hh);
    const char* Wb = (const char*)(g_wbf + (size_t)n0 * Hh);

    // stage fill: 8 x cp.async(16B) per thread (A 4 + B 4); 64B rows,
    // 4 chunks/row, swizzle chunk ^= (row>>1)&3
    auto issue = [&](int s, int kidx) {
        uint32_t aS = sbase + s * STG_BYTES;
        uint32_t bS = aS + A_U32 * 4;
        int kb = kidx * (KC * 2);
#pragma unroll
        for (int u = 0; u < 4; u++) {            // A: 512 chunks of 16B
            int c = tid + u * 128;
            int row = c >> 2, ch = c & 3;
            const char* g = Ab + (size_t)row * (Hh * 2) + kb + ch * 16;
            uint32_t d = aS + row * 64 + ((ch ^ ((row >> 1) & 3)) * 16);
            asm volatile("cp.async.cg.shared.global [%0], [%1], 16;" :: "r"(d), "l"(g));
        }
#pragma unroll
        for (int u = 0; u < 4; u++) {            // B: 512 chunks
            int c = tid + u * 128;
            int row = c >> 2, ch = c & 3;
            const char* g = Wb + (size_t)row * (Hh * 2) + kb + ch * 16;
            uint32_t d = bS + row * 64 + ((ch ^ ((row >> 1) & 3)) * 16);
            asm volatile("cp.async.cg.shared.global [%0], [%1], 16;" :: "r"(d), "l"(g));
        }
        asm volatile("cp.async.commit_group;" ::: "memory");
    };

    issue(0, 0); issue(1, 1); issue(2, 2); issue(3, 3);

    float acc[4][8][4];
#pragma unroll
    for (int i = 0; i < 4; i++)
#pragma unroll
        for (int j = 0; j < 8; j++)
#pragma unroll
            for (int r = 0; r < 4; r++) acc[i][j][r] = 0.f;

    // ldmatrix per-lane bases. Lane -> (row within 16, matrix k-group):
    int l7 = lane & 7;
    int a_row = l7 + ((lane >> 3) & 1) * 8;   // +8 for matrices 1,3
    int a_kg  = (lane >> 4) & 1;              // k-group for matrices 2,3
    int b_row = l7 + ((lane >> 4) & 1) * 8;   // +8 for matrices 2,3
    int b_kg  = (lane >> 3) & 1;              // k-group for matrices 1,3
    int sA = (a_row >> 1) & 3;                // swizzle term (row>>1)&3
    int sB = (b_row >> 1) & 3;
    // fully precomputed per-kstep addresses (add stage offset at use site)
    uint32_t aAdr[4][2], bAdr[4][2];
#pragma unroll
    for (int i = 0; i < 4; i++)
#pragma unroll
        for (int kk = 0; kk < 2; kk++)
            aAdr[i][kk] = sbase + (wm + i * 16 + a_row) * 64
                        + (uint32_t)(((2 * kk + a_kg) ^ sA) << 4);
#pragma unroll
    for (int jp = 0; jp < 4; jp++)
#pragma unroll
        for (int kk = 0; kk < 2; kk++)
            bAdr[jp][kk] = sbase + A_U32 * 4 + (wn + jp * 16 + b_row) * 64
                         + (uint32_t)(((2 * kk + b_kg) ^ sB) << 4);

    auto load_a = [&](uint32_t (&af)[4][4], uint32_t so, int kk) {
#pragma unroll
        for (int i = 0; i < 4; i++)
            LDMX4(af[i][0], af[i][1], af[i][2], af[i][3], aAdr[i][kk] + so);
    };
    auto load_b = [&](uint32_t (&bfr)[8][2], uint32_t so, int kk) {
#pragma unroll
        for (int jp = 0; jp < 4; jp++)
            LDMX4(bfr[2 * jp][0], bfr[2 * jp][1],
                  bfr[2 * jp + 1][0], bfr[2 * jp + 1][1], bAdr[jp][kk] + so);
    };
    auto mma_all = [&](uint32_t (&af)[4][4], uint32_t (&bfr)[8][2]) {
#pragma unroll
        for (int i = 0; i < 4; i++)
#pragma unroll
            for (int j = 0; j < 8; j++)
                asm volatile(
                    "mma.sync.aligned.m16n8k16.row.col.f32.bf16.bf16.f32 "
                    "{%0,%1,%2,%3}, {%4,%5,%6,%7}, {%8,%9}, {%0,%1,%2,%3};"
                    : "+f"(acc[i][j][0]), "+f"(acc[i][j][1]),
                      "+f"(acc[i][j][2]), "+f"(acc[i][j][3])
                    : "r"(af[i][0]), "r"(af[i][1]), "r"(af[i][2]), "r"(af[i][3]),
                      "r"(bfr[j][0]), "r"(bfr[j][1]));
    };

    uint32_t afp[4][4], bfp[8][2];      // prefetched kstep0 fragments
    uint32_t so = 0;                    // current chunk's stage byte offset
    int sI = 4;                         // next stage index to fill

    for (int ks = 0; ks < KCHUNKS; ks++) {
        // fills complete through ks+1 (prefetch target); 2 newest stay
        // outstanding => each fill has ~3 chunk-times of slack
        if (ks < KCHUNKS - 3)
            asm volatile("cp.async.wait_group 2;" ::: "memory");
        else
            asm volatile("cp.async.wait_group 0;" ::: "memory");
        __syncthreads();
        if (ks + 4 < KCHUNKS) {
            issue(sI, ks + 4);
            sI = (sI == NSTG - 1) ? 0 : sI + 1;
        }

        if (ks == 0) { load_a(afp, so, 0); load_b(bfp, so, 0); }   // startup

        mma_all(afp, bfp);              // kstep 0: fragments already resident
        {
            uint32_t af[4][4], bfr[8][2];
            load_a(af, so, 1);
            load_b(bfr, so, 1);
            mma_all(af, bfr);
        }
        uint32_t soN = (so == (NSTG - 1) * STG_BYTES) ? 0 : so + STG_BYTES;
        if (ks + 1 < KCHUNKS) {         // prefetch next chunk's kstep0 frags
            load_a(afp, soN, 0);
            load_b(bfp, soN, 0);
        }
        so = soN;
    }

    // Fused epilogue: part[m] = sum_n tanh(acc + bh[n]) * ww[n]
    float bhv[8][2], wwv[8][2];
#pragma unroll
    for (int j = 0; j < 8; j++) {
#pragma unroll
        for (int h = 0; h < 2; h++) {
            int n = n0 + wn + j * 8 + 2 * tig + h;
            bhv[j][h] = bh[n];
            wwv[j][h] = ww[n];
        }
    }
#pragma unroll
    for (int i = 0; i < 4; i++) {
        float p0 = 0.f, p1 = 0.f;
#pragma unroll
        for (int j = 0; j < 8; j++) {
            p0 += tanh_fast(acc[i][j][0] + bhv[j][0]) * wwv[j][0];
            p0 += tanh_fast(acc[i][j][1] + bhv[j][1]) * wwv[j][1];
            p1 += tanh_fast(acc[i][j][2] + bhv[j][0]) * wwv[j][0];
            p1 += tanh_fast(acc[i][j][3] + bhv[j][1]) * wwv[j][1];
        }
        p0 += __shfl_xor_sync(0xffffffffu, p0, 1);
        p0 += __shfl_xor_sync(0xffffffffu, p0, 2);
        p1 += __shfl_xor_sync(0xffffffffu, p1, 1);
        p1 += __shfl_xor_sync(0xffffffffu, p1, 2);
        if (tig == 0) {
            atomicAdd(&s_red[wm + i * 16 + gid], p0);
            atomicAdd(&s_red[wm + i * 16 + gid + 8], p1);
        }
    }
    __syncthreads();
    g_spart[blockIdx.x * Mtot + m0 + tid] = s_red[tid];
}

// ---------------------------------------------------------------------------
// softmax over T per batch row (sums the GX partial-score slabs)
// ---------------------------------------------------------------------------
__global__ void softmax_kernel() {
    __shared__ float red[Tt];
    int b = blockIdx.x;
    int t = threadIdx.x;
    float s = 0.f;
#pragma unroll
    for (int p = 0; p < GX; p++) s += g_spart[p * Mtot + b * Tt + t];
    red[t] = s;
    __syncthreads();
    for (int off = 256; off > 0; off >>= 1) {
        if (t < off) red[t] = fmaxf(red[t], red[t + off]);
        __syncthreads();
    }
    float mx = red[0];
    __syncthreads();
    float e = expf(s - mx);
    red[t] = e;
    __syncthreads();
    for (int off = 256; off > 0; off >>= 1) {
        if (t < off) red[t] += red[t + off];
        __syncthreads();
    }
    g_alpha[b * Tt + t] = e / red[0];
}

// ---------------------------------------------------------------------------
// r[b,h] += sum_t alpha[b,t]*hidden[b,t,h] — reads bf16 copy (half traffic),
// each thread covers an h-pair; T split 4 ways for MLP.
// ---------------------------------------------------------------------------
__global__ void wsum_kernel() {
    __shared__ float a_s[128];
    int seg = blockIdx.z;
    int b = blockIdx.y;
    int h2 = blockIdx.x * 256 + threadIdx.x;       // bf16x2 index, 0..511
    if (threadIdx.x < 128) a_s[threadIdx.x] = g_alpha[b * Tt + seg * 128 + threadIdx.x];
    __syncthreads();
    const __nv_bfloat162* hp = (const __nv_bfloat162*)g_hbf
        + ((size_t)b * Tt + seg * 128) * (Hh / 2) + h2;
    float ax[4], ay[4];
#pragma unroll
    for (int u = 0; u < 4; u++) { ax[u] = 0.f; ay[u] = 0.f; }
    for (int t = 0; t < 128; t += 4) {
#pragma unroll
        for (int u = 0; u < 4; u++) {
            float2 v = __bfloat1622float2(hp[(size_t)(t + u) * (Hh / 2)]);
            float a = a_s[t + u];
            ax[u] = fmaf(a, v.x, ax[u]);
            ay[u] = fmaf(a, v.y, ay[u]);
        }
    }
    atomicAdd(&g_r[b * Hh + 2 * h2],     (ax[0] + ax[1]) + (ax[2] + ax[3]));
    atomicAdd(&g_r[b * Hh + 2 * h2 + 1], (ay[0] + ay[1]) + (ay[2] + ay[3]));
}

// ---------------------------------------------------------------------------
// small GEMM: out[b,n] += V[b,:] . W[n,:]   (out pre-initialized with bias)
// blockIdx.z selects the p-path (r@W_p) or x-path (hidden_last@W_x).
// ---------------------------------------------------------------------------
__global__ __launch_bounds__(256)
void small_gemm_kernel(const float* __restrict__ hidden,
                       const float* __restrict__ W_p,
                       const float* __restrict__ W_x) {
    __shared__ float Vs[32][68];
    __shared__ float Ws[32][68];

    int sel = blockIdx.z;
    const float* W = sel ? W_x : W_p;
    const float* V;
    size_t vstride;
    if (sel) { V = hidden + (size_t)(Tt - 1) * Hh; vstride = (size_t)Tt * Hh; }
    else     { V = g_r; vstride = Hh; }

    int tid = threadIdx.x;
    int nBase = blockIdx.x * 64;
    int kBase = blockIdx.y * 128;

    int tn = tid & 15;
    int tb = tid >> 4;
    int lrow = tid >> 3;
    int lcol = (tid & 7) << 2;

    float acc[4][4];
#pragma unroll
    for (int i = 0; i < 4; i++)
#pragma unroll
        for (int j = 0; j < 4; j++) acc[i][j] = 0.f;

    for (int kc = 0; kc < 128; kc += 32) {
        int kg = kBase + kc;
        float4 v0 = *(const float4*)(V + (size_t)lrow * vstride + kg + lcol);
        float4 v1 = *(const float4*)(V + (size_t)(lrow + 32) * vstride + kg + lcol);
        float4 w0 = *(const float4*)(W + (size_t)(nBase + lrow) * Hh + kg + lcol);
        float4 w1 = *(const float4*)(W + (size_t)(nBase + lrow + 32) * Hh + kg + lcol);
        __syncthreads();
        Vs[lcol + 0][lrow] = v0.x; Vs[lcol + 1][lrow] = v0.y;
        Vs[lcol + 2][lrow] = v0.z; Vs[lcol + 3][lrow] = v0.w;
        Vs[lcol + 0][lrow + 32] = v1.x; Vs[lcol + 1][lrow + 32] = v1.y;
        Vs[lcol + 2][lrow + 32] = v1.z; Vs[lcol + 3][lrow + 32] = v1.w;
        Ws[lcol + 0][lrow] = w0.x; Ws[lcol + 1][lrow] = w0.y;
        Ws[lcol + 2][lrow] = w0.z; Ws[lcol + 3][lrow] = w0.w;
        Ws[lcol + 0][lrow + 32] = w1.x; Ws[lcol + 1][lrow + 32] = w1.y;
        Ws[lcol + 2][lrow + 32] = w1.z; Ws[lcol + 3][lrow + 32] = w1.w;
        __syncthreads();
#pragma unroll
        for (int k = 0; k < 32; k++) {
            float vb[4], wnv[4];
#pragma unroll
            for (int i = 0; i < 4; i++) vb[i] = Vs[k][tb * 4 + i];
#pragma unroll
            for (int j = 0; j < 4; j++) wnv[j] = Ws[k][tn * 4 + j];
#pragma unroll
            for (int i = 0; i < 4; i++)
#pragma unroll
                for (int j = 0; j < 4; j++)
                    acc[i][j] = fmaf(vb[i], wnv[j], acc[i][j]);
        }
    }

    float* out = sel ? g_x : g_p;
#pragma unroll
    for (int i = 0; i < 4; i++)
#pragma unroll
        for (int j = 0; j < 4; j++)
            atomicAdd(&out[(tb * 4 + i) * Hh + nBase + tn * 4 + j], acc[i][j]);
}

// ---------------------------------------------------------------------------
// output[b1,b2,h] = tanh(p[b1,h] + x[b2,h])
// ---------------------------------------------------------------------------
__global__ void output_kernel(float* __restrict__ out) {
    int h = blockIdx.x * 256 + threadIdx.x;
    int b2 = blockIdx.y;
    int b1 = blockIdx.z;
    out[((size_t)b1 * Bb + b2) * Hh + h] =
        tanhf(g_p[b1 * Hh + h] + g_x[b2 * Hh + h]);
}

// ---------------------------------------------------------------------------
// launch
// ---------------------------------------------------------------------------
extern "C" void kernel_launch(void* const* d_in, const int* in_sizes, int n_in,
                              void* d_out, int out_size) {
    (void)in_sizes; (void)n_in; (void)out_size;
    const float* hidden = (const float*)d_in[0];
    // d_in[1] aspect, d_in[4] W_v, d_in[5] b_v, d_in[7] w_b are provably dead
    // (softmax shift-invariance kills the per-batch-constant aspect branch).
    const float* W_h = (const float*)d_in[2];
    const float* b_h = (const float*)d_in[3];
    const float* w_w = (const float*)d_in[6];
    const float* W_p = (const float*)d_in[8];
    const float* b_p = (const float*)d_in[9];
    const float* W_x = (const float*)d_in[10];
    const float* b_x = (const float*)d_in[11];
    float* out = (float*)d_out;

    cudaFuncSetAttribute(gemm_scores_tc,
                         cudaFuncAttributeMaxDynamicSharedMemorySize, SMEM_BYTES);

    __nv_bfloat16* hbf = nullptr;
    __nv_bfloat16* wbf = nullptr;
    cudaGetSymbolAddress((void**)&hbf, g_hbf);
    cudaGetSymbolAddress((void**)&wbf, g_wbf);

    cvt_kernel<<<(Mtot * (Hh / 8)) / 256, 256>>>(hidden, hbf);   // 16384 blocks
    cvt_kernel<<<(Hh * (Hh / 8)) / 256, 256>>>(W_h, wbf);        // 512 blocks
    init_kernel<<<256, 256>>>(b_p, b_x);
    gemm_scores_tc<<<dim3(GX, Mtot / MT), 128, SMEM_BYTES>>>(b_h, w_w);
    softmax_kernel<<<Bb, Tt>>>();
    wsum_kernel<<<dim3(Hh / 512, Bb, 4), 256>>>();
    small_gemm_kernel<<<dim3(Hh / 64, Hh / 128, 2), 256>>>(hidden, W_p, W_x);
    output_kernel<<<dim3(Hh / 256, Bb, Bb), 256>>>(out);
}

// round 14
// speedup vs baseline: 11.1569x; 1.0227x over previous
#include <cuda_runtime.h>
#include <cuda_bf16.h>
#include <math.h>
#include <stdint.h>

// ---------------------------------------------------------------------------
// Problem constants
// ---------------------------------------------------------------------------
#define Bb 64
#define Tt 512
#define Hh 1024
#define Mtot (Bb * Tt)   // 32768

// Big-GEMM tiling: CTA 128x128, 4 warps (64x64 each), 2 CTAs/SM
#define MT 128
#define NT 128
#define KC 32                        // K per smem stage (32 bf16 = 64B rows)
#define NSTG 6
#define KCHUNKS (Hh / KC)            // 32
#define GX (Hh / NT)                 // 8
#define A_U32 (MT * KC / 2)          // 2048 uint32
#define STG_U32 ((MT + NT) * KC / 2) // 4096 uint32 = 16KB/stage
#define STG_BYTES (STG_U32 * 4)
#define SMEM_U32 (NSTG * STG_U32 + 128)
#define SMEM_BYTES (SMEM_U32 * 4)    // 98816

// prep_kernel block ranges
#define PREP_H_BLKS (Mtot * Hh / 8 / 256)   // 16384
#define PREP_W_BLKS (Hh * Hh / 8 / 256)     // 512
#define PREP_I_BLKS (Bb * Hh / 256)         // 256 (init: 65536 elems/256thr -> 256 blks? no: 64*1024/256=256)
#define PREP_BLKS (PREP_H_BLKS + PREP_W_BLKS + PREP_I_BLKS)

// wsum segmentation
#define WSEG 8
#define WROWS (Tt / WSEG)            // 64

// ---------------------------------------------------------------------------
// Scratch (device globals: no allocation allowed)
// ---------------------------------------------------------------------------
__device__ __align__(256) __nv_bfloat16 g_hbf[(size_t)Mtot * Hh];  // 64MB
__device__ __align__(256) __nv_bfloat16 g_wbf[(size_t)Hh * Hh];    // 2MB
__device__ float g_spart[GX * Mtot];   // per-N-tile partial scores (1MB)
__device__ float g_alpha[Mtot];
__device__ float g_r[Bb * Hh];
__device__ float g_p[Bb * Hh];
__device__ float g_x[Bb * Hh];

// ---------------------------------------------------------------------------
// helpers
// ---------------------------------------------------------------------------
__device__ __forceinline__ uint32_t smem_u32(const void* p) {
    uint32_t a;
    asm("{ .reg .u64 t; cvta.to.shared.u64 t, %1; cvt.u32.u64 %0, t; }" : "=r"(a) : "l"(p));
    return a;
}
__device__ __forceinline__ float tanh_fast(float x) {
    float y;
    asm("tanh.approx.f32 %0, %1;" : "=f"(y) : "f"(x));
    return y;
}
__device__ __forceinline__ uint32_t pack_bf2(float lo, float hi) {
    __nv_bfloat162 v = __float22bfloat162_rn(make_float2(lo, hi));
    return *(uint32_t*)&v;
}
#define LDMX4(d0, d1, d2, d3, addr) \
    asm volatile("ldmatrix.sync.aligned.m8n8.x4.shared.b16 {%0,%1,%2,%3}, [%4];" \
                 : "=r"(d0), "=r"(d1), "=r"(d2), "=r"(d3) : "r"(addr))

// ---------------------------------------------------------------------------
// prep: fused fp32->bf16 converts (hidden, W_h) + bias-preload init.
// One launch instead of three; branch on block range.
// ---------------------------------------------------------------------------
__global__ void prep_kernel(const float* __restrict__ hidden,
                            const float* __restrict__ W_h,
                            const float* __restrict__ b_p,
                            const float* __restrict__ b_x) {
    int blk = blockIdx.x;
    if (blk < PREP_H_BLKS + PREP_W_BLKS) {
        const float* s;
        __nv_bfloat16* d;
        size_t i;
        if (blk < PREP_H_BLKS) {
            s = hidden; d = g_hbf;
            i = (size_t)blk * 256 + threadIdx.x;
        } else {
            s = W_h; d = g_wbf;
            i = (size_t)(blk - PREP_H_BLKS) * 256 + threadIdx.x;
        }
        const float4* s4 = (const float4*)s;
        float4 v0 = s4[2 * i], v1 = s4[2 * i + 1];
        uint4 o;
        o.x = pack_bf2(v0.x, v0.y);
        o.y = pack_bf2(v0.z, v0.w);
        o.z = pack_bf2(v1.x, v1.y);
        o.w = pack_bf2(v1.z, v1.w);
        ((uint4*)d)[i] = o;
    } else {
        int i = (blk - PREP_H_BLKS - PREP_W_BLKS) * 256 + threadIdx.x;   // 0..65535
        g_r[i] = 0.f;
        g_p[i] = b_p[i & (Hh - 1)];
        g_x[i] = b_x[i & (Hh - 1)];
    }
}

// ---------------------------------------------------------------------------
// Big GEMM (M=32768,N=1024,K=1024) on mma.sync m16n8k16 bf16, fused
// tanh*w_w score-reduction epilogue. CTA tile 128x128, 4 warps (64x64),
// 6-stage cp.async pipeline, 2 CTAs/SM, ldmatrix.x4 fragment loads.
// kstep0 frags prefetched across the barrier; kstep1 ldmatrix issued
// BEFORE kstep0's MMA block so its latency hides under those MMAs.
// ---------------------------------------------------------------------------
__global__ __launch_bounds__(128, 2)
void gemm_scores_tc(const float* __restrict__ bh,
                    const float* __restrict__ ww) {
    extern __shared__ uint32_t sm[];
    float* s_red = (float*)(sm + NSTG * STG_U32);

    int tid = threadIdx.x;
    int w = tid >> 5, lane = tid & 31;
    int gid = lane >> 2, tig = lane & 3;
    int wm = (w >> 1) * 64;         // 0 / 64
    int wn = (w & 1) * 64;          // 0 / 64
    int m0 = blockIdx.y * MT;
    int n0 = blockIdx.x * NT;

    s_red[tid] = 0.f;

    uint32_t sbase = smem_u32(sm);
    const char* Ab = (const char*)(g_hbf + (size_t)m0 * Hh);
    const char* Wb = (const char*)(g_wbf + (size_t)n0 * Hh);

    // stage fill: 8 x cp.async(16B) per thread (A 4 + B 4); 64B rows,
    // 4 chunks/row, swizzle chunk ^= (row>>1)&3
    auto issue = [&](int s, int kidx) {
        uint32_t aS = sbase + s * STG_BYTES;
        uint32_t bS = aS + A_U32 * 4;
        int kb = kidx * (KC * 2);
#pragma unroll
        for (int u = 0; u < 4; u++) {            // A: 512 chunks of 16B
            int c = tid + u * 128;
            int row = c >> 2, ch = c & 3;
            const char* g = Ab + (size_t)row * (Hh * 2) + kb + ch * 16;
            uint32_t d = aS + row * 64 + ((ch ^ ((row >> 1) & 3)) * 16);
            asm volatile("cp.async.cg.shared.global [%0], [%1], 16;" :: "r"(d), "l"(g));
        }
#pragma unroll
        for (int u = 0; u < 4; u++) {            // B: 512 chunks
            int c = tid + u * 128;
            int row = c >> 2, ch = c & 3;
            const char* g = Wb + (size_t)row * (Hh * 2) + kb + ch * 16;
            uint32_t d = bS + row * 64 + ((ch ^ ((row >> 1) & 3)) * 16);
            asm volatile("cp.async.cg.shared.global [%0], [%1], 16;" :: "r"(d), "l"(g));
        }
        asm volatile("cp.async.commit_group;" ::: "memory");
    };

    issue(0, 0); issue(1, 1); issue(2, 2); issue(3, 3);

    float acc[4][8][4];
#pragma unroll
    for (int i = 0; i < 4; i++)
#pragma unroll
        for (int j = 0; j < 8; j++)
#pragma unroll
            for (int r = 0; r < 4; r++) acc[i][j][r] = 0.f;

    // ldmatrix per-lane bases. Lane -> (row within 16, matrix k-group):
    int l7 = lane & 7;
    int a_row = l7 + ((lane >> 3) & 1) * 8;   // +8 for matrices 1,3
    int a_kg  = (lane >> 4) & 1;              // k-group for matrices 2,3
    int b_row = l7 + ((lane >> 4) & 1) * 8;   // +8 for matrices 2,3
    int b_kg  = (lane >> 3) & 1;              // k-group for matrices 1,3
    int sA = (a_row >> 1) & 3;                // swizzle term (row>>1)&3
    int sB = (b_row >> 1) & 3;
    // fully precomputed per-kstep addresses (add stage offset at use site)
    uint32_t aAdr[4][2], bAdr[4][2];
#pragma unroll
    for (int i = 0; i < 4; i++)
#pragma unroll
        for (int kk = 0; kk < 2; kk++)
            aAdr[i][kk] = sbase + (wm + i * 16 + a_row) * 64
                        + (uint32_t)(((2 * kk + a_kg) ^ sA) << 4);
#pragma unroll
    for (int jp = 0; jp < 4; jp++)
#pragma unroll
        for (int kk = 0; kk < 2; kk++)
            bAdr[jp][kk] = sbase + A_U32 * 4 + (wn + jp * 16 + b_row) * 64
                         + (uint32_t)(((2 * kk + b_kg) ^ sB) << 4);

    auto load_a = [&](uint32_t (&af)[4][4], uint32_t so, int kk) {
#pragma unroll
        for (int i = 0; i < 4; i++)
            LDMX4(af[i][0], af[i][1], af[i][2], af[i][3], aAdr[i][kk] + so);
    };
    auto load_b = [&](uint32_t (&bfr)[8][2], uint32_t so, int kk) {
#pragma unroll
        for (int jp = 0; jp < 4; jp++)
            LDMX4(bfr[2 * jp][0], bfr[2 * jp][1],
                  bfr[2 * jp + 1][0], bfr[2 * jp + 1][1], bAdr[jp][kk] + so);
    };
    auto mma_all = [&](uint32_t (&af)[4][4], uint32_t (&bfr)[8][2]) {
#pragma unroll
        for (int i = 0; i < 4; i++)
#pragma unroll
            for (int j = 0; j < 8; j++)
                asm volatile(
                    "mma.sync.aligned.m16n8k16.row.col.f32.bf16.bf16.f32 "
                    "{%0,%1,%2,%3}, {%4,%5,%6,%7}, {%8,%9}, {%0,%1,%2,%3};"
                    : "+f"(acc[i][j][0]), "+f"(acc[i][j][1]),
                      "+f"(acc[i][j][2]), "+f"(acc[i][j][3])
                    : "r"(af[i][0]), "r"(af[i][1]), "r"(af[i][2]), "r"(af[i][3]),
                      "r"(bfr[j][0]), "r"(bfr[j][1]));
    };

    uint32_t afp[4][4], bfp[8][2];      // prefetched kstep0 fragments
    uint32_t so = 0;                    // current chunk's stage byte offset
    int sI = 4;                         // next stage index to fill

    for (int ks = 0; ks < KCHUNKS; ks++) {
        if (ks < KCHUNKS - 3)
            asm volatile("cp.async.wait_group 2;" ::: "memory");
        else
            asm volatile("cp.async.wait_group 0;" ::: "memory");
        __syncthreads();
        if (ks + 4 < KCHUNKS) {
            issue(sI, ks + 4);
            sI = (sI == NSTG - 1) ? 0 : sI + 1;
        }

        if (ks == 0) { load_a(afp, so, 0); load_b(bfp, so, 0); }   // startup

        // issue kstep1 loads FIRST so their latency hides under kstep0 MMAs
        uint32_t af[4][4], bfr[8][2];
        load_a(af, so, 1);
        load_b(bfr, so, 1);
        mma_all(afp, bfp);              // kstep 0: fragments already resident
        mma_all(af, bfr);               // kstep 1: latency covered above

        uint32_t soN = (so == (NSTG - 1) * STG_BYTES) ? 0 : so + STG_BYTES;
        if (ks + 1 < KCHUNKS) {         // prefetch next chunk's kstep0 frags
            load_a(afp, soN, 0);
            load_b(bfp, soN, 0);
        }
        so = soN;
    }

    // Fused epilogue: part[m] = sum_n tanh(acc + bh[n]) * ww[n]
    float bhv[8][2], wwv[8][2];
#pragma unroll
    for (int j = 0; j < 8; j++) {
#pragma unroll
        for (int h = 0; h < 2; h++) {
            int n = n0 + wn + j * 8 + 2 * tig + h;
            bhv[j][h] = bh[n];
            wwv[j][h] = ww[n];
        }
    }
#pragma unroll
    for (int i = 0; i < 4; i++) {
        float p0 = 0.f, p1 = 0.f;
#pragma unroll
        for (int j = 0; j < 8; j++) {
            p0 += tanh_fast(acc[i][j][0] + bhv[j][0]) * wwv[j][0];
            p0 += tanh_fast(acc[i][j][1] + bhv[j][1]) * wwv[j][1];
            p1 += tanh_fast(acc[i][j][2] + bhv[j][0]) * wwv[j][0];
            p1 += tanh_fast(acc[i][j][3] + bhv[j][1]) * wwv[j][1];
        }
        p0 += __shfl_xor_sync(0xffffffffu, p0, 1);
        p0 += __shfl_xor_sync(0xffffffffu, p0, 2);
        p1 += __shfl_xor_sync(0xffffffffu, p1, 1);
        p1 += __shfl_xor_sync(0xffffffffu, p1, 2);
        if (tig == 0) {
            atomicAdd(&s_red[wm + i * 16 + gid], p0);
            atomicAdd(&s_red[wm + i * 16 + gid + 8], p1);
        }
    }
    __syncthreads();
    g_spart[blockIdx.x * Mtot + m0 + tid] = s_red[tid];
}

// ---------------------------------------------------------------------------
// softmax over T per batch row (sums the GX partial-score slabs)
// ---------------------------------------------------------------------------
__global__ void softmax_kernel() {
    __shared__ float red[Tt];
    int b = blockIdx.x;
    int t = threadIdx.x;
    float s = 0.f;
#pragma unroll
    for (int p = 0; p < GX; p++) s += g_spart[p * Mtot + b * Tt + t];
    red[t] = s;
    __syncthreads();
    for (int off = 256; off > 0; off >>= 1) {
        if (t < off) red[t] = fmaxf(red[t], red[t + off]);
        __syncthreads();
    }
    float mx = red[0];
    __syncthreads();
    float e = expf(s - mx);
    red[t] = e;
    __syncthreads();
    for (int off = 256; off > 0; off >>= 1) {
        if (t < off) red[t] += red[t + off];
        __syncthreads();
    }
    g_alpha[b * Tt + t] = e / red[0];
}

// ---------------------------------------------------------------------------
// r[b,h] += sum_t alpha[b,t]*hidden[b,t,h] — reads bf16 copy, T split 8 ways
// for memory-level parallelism; each thread covers an h-pair.
// ---------------------------------------------------------------------------
__global__ void wsum_kernel() {
    __shared__ float a_s[WROWS];
    int seg = blockIdx.z;
    int b = blockIdx.y;
    int h2 = blockIdx.x * 256 + threadIdx.x;       // bf16x2 index, 0..511
    if (threadIdx.x < WROWS)
        a_s[threadIdx.x] = g_alpha[b * Tt + seg * WROWS + threadIdx.x];
    __syncthreads();
    const __nv_bfloat162* hp = (const __nv_bfloat162*)g_hbf
        + ((size_t)b * Tt + seg * WROWS) * (Hh / 2) + h2;
    float ax[4], ay[4];
#pragma unroll
    for (int u = 0; u < 4; u++) { ax[u] = 0.f; ay[u] = 0.f; }
    for (int t = 0; t < WROWS; t += 4) {
#pragma unroll
        for (int u = 0; u < 4; u++) {
            float2 v = __bfloat1622float2(hp[(size_t)(t + u) * (Hh / 2)]);
            float a = a_s[t + u];
            ax[u] = fmaf(a, v.x, ax[u]);
            ay[u] = fmaf(a, v.y, ay[u]);
        }
    }
    atomicAdd(&g_r[b * Hh + 2 * h2],     (ax[0] + ax[1]) + (ax[2] + ax[3]));
    atomicAdd(&g_r[b * Hh + 2 * h2 + 1], (ay[0] + ay[1]) + (ay[2] + ay[3]));
}

// ---------------------------------------------------------------------------
// small GEMM: out[b,n] += V[b,:] . W[n,:]   (out pre-initialized with bias)
// blockIdx.z selects the p-path (r@W_p) or x-path (hidden_last@W_x).
// ---------------------------------------------------------------------------
__global__ __launch_bounds__(256)
void small_gemm_kernel(const float* __restrict__ hidden,
                       const float* __restrict__ W_p,
                       const float* __restrict__ W_x) {
    __shared__ float Vs[32][68];
    __shared__ float Ws[32][68];

    int sel = blockIdx.z;
    const float* W = sel ? W_x : W_p;
    const float* V;
    size_t vstride;
    if (sel) { V = hidden + (size_t)(Tt - 1) * Hh; vstride = (size_t)Tt * Hh; }
    else     { V = g_r; vstride = Hh; }

    int tid = threadIdx.x;
    int nBase = blockIdx.x * 64;
    int kBase = blockIdx.y * 128;

    int tn = tid & 15;
    int tb = tid >> 4;
    int lrow = tid >> 3;
    int lcol = (tid & 7) << 2;

    float acc[4][4];
#pragma unroll
    for (int i = 0; i < 4; i++)
#pragma unroll
        for (int j = 0; j < 4; j++) acc[i][j] = 0.f;

    for (int kc = 0; kc < 128; kc += 32) {
        int kg = kBase + kc;
        float4 v0 = *(const float4*)(V + (size_t)lrow * vstride + kg + lcol);
        float4 v1 = *(const float4*)(V + (size_t)(lrow + 32) * vstride + kg + lcol);
        float4 w0 = *(const float4*)(W + (size_t)(nBase + lrow) * Hh + kg + lcol);
        float4 w1 = *(const float4*)(W + (size_t)(nBase + lrow + 32) * Hh + kg + lcol);
        __syncthreads();
        Vs[lcol + 0][lrow] = v0.x; Vs[lcol + 1][lrow] = v0.y;
        Vs[lcol + 2][lrow] = v0.z; Vs[lcol + 3][lrow] = v0.w;
        Vs[lcol + 0][lrow + 32] = v1.x; Vs[lcol + 1][lrow + 32] = v1.y;
        Vs[lcol + 2][lrow + 32] = v1.z; Vs[lcol + 3][lrow + 32] = v1.w;
        Ws[lcol + 0][lrow] = w0.x; Ws[lcol + 1][lrow] = w0.y;
        Ws[lcol + 2][lrow] = w0.z; Ws[lcol + 3][lrow] = w0.w;
        Ws[lcol + 0][lrow + 32] = w1.x; Ws[lcol + 1][lrow + 32] = w1.y;
        Ws[lcol + 2][lrow + 32] = w1.z; Ws[lcol + 3][lrow + 32] = w1.w;
        __syncthreads();
#pragma unroll
        for (int k = 0; k < 32; k++) {
            float vb[4], wnv[4];
#pragma unroll
            for (int i = 0; i < 4; i++) vb[i] = Vs[k][tb * 4 + i];
#pragma unroll
            for (int j = 0; j < 4; j++) wnv[j] = Ws[k][tn * 4 + j];
#pragma unroll
            for (int i = 0; i < 4; i++)
#pragma unroll
                for (int j = 0; j < 4; j++)
                    acc[i][j] = fmaf(vb[i], wnv[j], acc[i][j]);
        }
    }

    float* out = sel ? g_x : g_p;
#pragma unroll
    for (int i = 0; i < 4; i++)
#pragma unroll
        for (int j = 0; j < 4; j++)
            atomicAdd(&out[(tb * 4 + i) * Hh + nBase + tn * 4 + j], acc[i][j]);
}

// ---------------------------------------------------------------------------
// output[b1,b2,h] = tanh(p[b1,h] + x[b2,h])
// ---------------------------------------------------------------------------
__global__ void output_kernel(float* __restrict__ out) {
    int h = blockIdx.x * 256 + threadIdx.x;
    int b2 = blockIdx.y;
    int b1 = blockIdx.z;
    out[((size_t)b1 * Bb + b2) * Hh + h] =
        tanhf(g_p[b1 * Hh + h] + g_x[b2 * Hh + h]);
}

// ---------------------------------------------------------------------------
// launch
// ---------------------------------------------------------------------------
extern "C" void kernel_launch(void* const* d_in, const int* in_sizes, int n_in,
                              void* d_out, int out_size) {
    (void)in_sizes; (void)n_in; (void)out_size;
    const float* hidden = (const float*)d_in[0];
    // d_in[1] aspect, d_in[4] W_v, d_in[5] b_v, d_in[7] w_b are provably dead
    // (softmax shift-invariance kills the per-batch-constant aspect branch).
    const float* W_h = (const float*)d_in[2];
    const float* b_h = (const float*)d_in[3];
    const float* w_w = (const float*)d_in[6];
    const float* W_p = (const float*)d_in[8];
    const float* b_p = (const float*)d_in[9];
    const float* W_x = (const float*)d_in[10];
    const float* b_x = (const float*)d_in[11];
    float* out = (float*)d_out;

    cudaFuncSetAttribute(gemm_scores_tc,
                         cudaFuncAttributeMaxDynamicSharedMemorySize, SMEM_BYTES);

    prep_kernel<<<PREP_BLKS, 256>>>(hidden, W_h, b_p, b_x);
    gemm_scores_tc<<<dim3(GX, Mtot / MT), 128, SMEM_BYTES>>>(b_h, w_w);
    softmax_kernel<<<Bb, Tt>>>();
    wsum_kernel<<<dim3(Hh / 512, Bb, WSEG), 256>>>();
    small_gemm_kernel<<<dim3(Hh / 64, Hh / 128, 2), 256>>>(hidden, W_p, W_x);
    output_kernel<<<dim3(Hh / 256, Bb, Bb), 256>>>(out);
}